// round 5
// baseline (speedup 1.0000x reference)
#include <cuda_runtime.h>
#include <cstdint>

#define BATCH 16
#define CDIM 256
#define NPIX 10000
#define KDET 100
#define KREC 25
#define TPAD 20
#define PPARTS 8

// ---------------- scratch (static device globals) ----------------
__device__ float g_ppq[PPARTS * 6 * 2500];   // partial projections of pe (50x50 grid)
__device__ float g_pq[6 * 2500];             // pos projections on 50x50 grid
__device__ float g_pp[6 * NPIX];             // resized pos projections [6, N]
__device__ unsigned g_keys[BATCH * NPIX];    // monotone-transformed margin keys
__device__ int g_idx[BATCH * KDET];          // top-100 indices per batch

// ---------------- f32x2 packed helpers ----------------
__device__ __forceinline__ unsigned long long pk2(float a, float b) {
    unsigned long long r;
    asm("mov.b64 %0, {%1,%2};" : "=l"(r) : "f"(a), "f"(b));
    return r;
}
__device__ __forceinline__ void upk2(unsigned long long v, float& a, float& b) {
    asm("mov.b64 {%0,%1}, %2;" : "=f"(a), "=f"(b) : "l"(v));
}
__device__ __forceinline__ unsigned long long fma2(unsigned long long a, unsigned long long b, unsigned long long c) {
    unsigned long long d;
    asm("fma.rn.f32x2 %0, %1, %2, %3;" : "=l"(d) : "l"(a), "l"(b), "l"(c));
    return d;
}
__device__ __forceinline__ unsigned key_xform(float f) {
    unsigned u = __float_as_uint(f);
    return (u & 0x80000000u) ? ~u : (u | 0x80000000u);
}

// ---------------- P1: project pe (256ch, 50x50) onto 6 weight rows, split over C ----------------
__global__ void pos_proj_part_kernel(const float* __restrict__ pe,
                                     const float* __restrict__ Wc, const float* __restrict__ Wb) {
    __shared__ float ws[6 * 256];
    int tid = threadIdx.x;
    for (int i = tid; i < 512; i += blockDim.x) ws[i] = Wc[i];
    for (int i = tid; i < 1024; i += blockDim.x) ws[512 + i] = Wb[i];
    __syncthreads();
    int id = blockIdx.x * blockDim.x + tid;
    if (id >= PPARTS * 2500) return;
    int part = id / 2500, pix = id % 2500;
    int c0 = part * 32;
    float a0 = 0, a1 = 0, a2 = 0, a3 = 0, a4 = 0, a5 = 0;
    #pragma unroll 8
    for (int i = 0; i < 32; i++) {
        int c = c0 + i;
        float p = __ldg(pe + (size_t)c * 2500 + pix);
        a0 += p * ws[c];        a1 += p * ws[256 + c];
        a2 += p * ws[512 + c];  a3 += p * ws[768 + c];
        a4 += p * ws[1024 + c]; a5 += p * ws[1280 + c];
    }
    float* o = g_ppq + (size_t)part * 6 * 2500 + pix;
    o[0] = a0; o[2500] = a1; o[5000] = a2; o[7500] = a3; o[10000] = a4; o[12500] = a5;
}

// ---------------- P2: reduce 8 partials ----------------
__global__ void pos_proj_reduce_kernel() {
    int id = blockIdx.x * blockDim.x + threadIdx.x;
    if (id >= 6 * 2500) return;
    float s = 0.f;
    #pragma unroll
    for (int p = 0; p < PPARTS; p++) s += g_ppq[(size_t)p * 6 * 2500 + id];
    g_pq[id] = s;
}

// ---------------- P3: bilinear resize the 6 projected channels 50x50 -> 100x100 ----------------
__global__ void resize6_kernel() {
    int id = blockIdx.x * blockDim.x + threadIdx.x;
    if (id >= 6 * NPIX) return;
    int w = id / NPIX, n = id % NPIX;
    int y = n / 100, x = n % 100;
    float sy = (y + 0.5f) * 0.5f - 0.5f; sy = fminf(fmaxf(sy, 0.f), 49.f);
    int y0 = (int)floorf(sy); int y1 = min(y0 + 1, 49); float ty = sy - (float)y0;
    float sx = (x + 0.5f) * 0.5f - 0.5f; sx = fminf(fmaxf(sx, 0.f), 49.f);
    int x0 = (int)floorf(sx); int x1 = min(x0 + 1, 49); float tx = sx - (float)x0;
    const float* p = g_pq + (size_t)w * 2500;
    float v00 = p[y0 * 50 + x0], v01 = p[y0 * 50 + x1];
    float v10 = p[y1 * 50 + x0], v11 = p[y1 * 50 + x1];
    float r0 = v00 * (1.f - ty) + v10 * ty;
    float r1 = v01 * (1.f - ty) + v11 * ty;
    g_pp[(size_t)w * NPIX + n] = r0 * (1.f - tx) + r1 * tx;
}

// ---------------- B: stream x once, 2px/thread, f32x2; emit cls/bbox/keys ----------------
__global__ void __launch_bounds__(128) main_pass_kernel(
        const float* __restrict__ x,
        const float* __restrict__ bc, const float* __restrict__ bb,
        const float* __restrict__ Wc, const float* __restrict__ Wb,
        float* __restrict__ out_cls, float* __restrict__ out_bb) {
    __shared__ unsigned long long ws2[6 * 256];   // duplicated (w,w) pairs, 12 KB
    int tid = threadIdx.x;
    for (int i = tid; i < 1536; i += 128) {
        float v = (i < 512) ? Wc[i] : Wb[i - 512];
        ws2[i] = pk2(v, v);
    }
    __syncthreads();
    int id = blockIdx.x * 128 + tid;        // 80000 items, 2px each
    int b = id / (NPIX / 2);
    int n2 = (id % (NPIX / 2)) * 2;
    const float* base = x + (size_t)b * CDIM * NPIX + n2;
    unsigned long long acc0 = 0, acc1 = 0, acc2 = 0, acc3 = 0, acc4 = 0, acc5 = 0;
    #pragma unroll 8
    for (int c = 0; c < 256; c++) {
        unsigned long long v = __ldg(reinterpret_cast<const unsigned long long*>(base + (size_t)c * NPIX));
        acc0 = fma2(v, ws2[c], acc0);
        acc1 = fma2(v, ws2[256 + c], acc1);
        acc2 = fma2(v, ws2[512 + c], acc2);
        acc3 = fma2(v, ws2[768 + c], acc3);
        acc4 = fma2(v, ws2[1024 + c], acc4);
        acc5 = fma2(v, ws2[1280 + c], acc5);
    }
    float a0x, a0y, a1x, a1y, a2x, a2y, a3x, a3y, a4x, a4y, a5x, a5y;
    upk2(acc0, a0x, a0y); upk2(acc1, a1x, a1y); upk2(acc2, a2x, a2y);
    upk2(acc3, a3x, a3y); upk2(acc4, a4x, a4y); upk2(acc5, a5x, a5y);
    float2 p0 = *reinterpret_cast<const float2*>(g_pp + 0 * NPIX + n2);
    float2 p1 = *reinterpret_cast<const float2*>(g_pp + 1 * NPIX + n2);
    float2 p2 = *reinterpret_cast<const float2*>(g_pp + 2 * NPIX + n2);
    float2 p3 = *reinterpret_cast<const float2*>(g_pp + 3 * NPIX + n2);
    float2 p4 = *reinterpret_cast<const float2*>(g_pp + 4 * NPIX + n2);
    float2 p5 = *reinterpret_cast<const float2*>(g_pp + 5 * NPIX + n2);
    float bc0 = bc[0], bc1 = bc[1];
    float bb0 = bb[0], bb1 = bb[1], bb2 = bb[2], bb3 = bb[3];
    float l0x = a0x + p0.x + bc0, l0y = a0y + p0.y + bc0;
    float l1x = a1x + p1.x + bc1, l1y = a1y + p1.y + bc1;
    size_t co = ((size_t)b * NPIX + n2) * 2;
    *reinterpret_cast<float4*>(out_cls + co) = make_float4(l0x, l1x, l0y, l1y);
    size_t bo = ((size_t)b * NPIX + n2) * 4;
    *reinterpret_cast<float4*>(out_bb + bo) =
        make_float4(a2x + p2.x + bb0, a3x + p3.x + bb1, a4x + p4.x + bb2, a5x + p5.x + bb3);
    *reinterpret_cast<float4*>(out_bb + bo + 4) =
        make_float4(a2y + p2.y + bb0, a3y + p3.y + bb1, a4y + p4.y + bb2, a5y + p5.y + bb3);
    uint2 kk = make_uint2(key_xform(l1x - l0x), key_xform(l1y - l0y));
    *reinterpret_cast<uint2*>(g_keys + (size_t)b * NPIX + n2) = kk;
}

// ---------------- C: exact per-batch top-100 (value desc, index asc) ----------------
// dyn smem: cand[256] ull @0 | keys[NPIX] u32 @2048 | hist[2048] u32 @42048 | tot[257] u32 @50240
#define TK_SMEM (50240 + 260 * 4)
__global__ void __launch_bounds__(1024) topk_kernel() {
    extern __shared__ char sm[];
    unsigned long long* cand = reinterpret_cast<unsigned long long*>(sm);
    unsigned* keys = reinterpret_cast<unsigned*>(sm + 2048);
    unsigned* histv = reinterpret_cast<unsigned*>(sm + 42048);
    unsigned* tot = reinterpret_cast<unsigned*>(sm + 50240);
    __shared__ unsigned s_prefix;
    __shared__ int s_kk, s_cnt;
    int b = blockIdx.x, tid = threadIdx.x;

    for (int i = tid; i < NPIX; i += 1024) keys[i] = g_keys[(size_t)b * NPIX + i];
    if (tid == 0) { s_prefix = 0u; s_kk = KDET; s_cnt = 0; }
    __syncthreads();

    #pragma unroll
    for (int pass = 0; pass < 4; pass++) {
        int shift = 24 - 8 * pass;
        unsigned himask = (pass == 0) ? 0u : (0xFFFFFFFFu << (shift + 8));
        for (int i = tid; i < 2048; i += 1024) histv[i] = 0;
        __syncthreads();
        unsigned prefix = s_prefix;
        int kk = s_kk;
        unsigned* myh = histv + ((tid >> 5) & 7) * 256;
        for (int i = tid; i < NPIX; i += 1024) {
            unsigned u = keys[i];
            if (((u ^ prefix) & himask) == 0) atomicAdd(&myh[(u >> shift) & 255], 1u);
        }
        __syncthreads();
        if (tid < 256) {
            unsigned s = 0;
            #pragma unroll
            for (int cp = 0; cp < 8; cp++) s += histv[cp * 256 + tid];
            tot[tid] = s;
        }
        __syncthreads();
        #pragma unroll
        for (int step = 1; step < 256; step <<= 1) {
            unsigned v = 0;
            if (tid < 256) v = tot[tid] + ((tid + step < 256) ? tot[tid + step] : 0u);
            __syncthreads();
            if (tid < 256) tot[tid] = v;
            __syncthreads();
        }
        if (tid < 256) {
            unsigned Sb = tot[tid];
            unsigned Sb1 = (tid < 255) ? tot[tid + 1] : 0u;
            if (Sb >= (unsigned)kk && Sb1 < (unsigned)kk) {
                s_prefix = prefix | ((unsigned)tid << shift);
                s_kk = kk - (int)Sb1;
            }
        }
        __syncthreads();
    }
    unsigned T = s_prefix;

    for (int i = tid; i < NPIX; i += 1024) {
        unsigned u = keys[i];
        if (u >= T) {
            int p = atomicAdd(&s_cnt, 1);
            if (p < 256)
                cand[p] = ((unsigned long long)u << 32) | (unsigned)(~(unsigned)i);
        }
    }
    __syncthreads();
    int cnt = min(s_cnt, 256);
    for (int i = cnt + tid; i < 256; i += 1024) cand[i] = 0ull;
    __syncthreads();

    for (int ksz = 2; ksz <= 256; ksz <<= 1) {
        for (int j = ksz >> 1; j > 0; j >>= 1) {
            if (tid < 256) {
                int l = tid ^ j;
                if (l > tid) {
                    unsigned long long a = cand[tid], c2 = cand[l];
                    bool dirDesc = ((tid & ksz) == 0);
                    if ((a < c2) == dirDesc) { cand[tid] = c2; cand[l] = a; }
                }
            }
            __syncthreads();
        }
    }
    if (tid < KDET)
        g_idx[b * KDET + tid] = (int)(~((unsigned)(cand[tid] & 0xFFFFFFFFull)));
}

// ---------------- MLP: f32x2 token pairs, LDS.128 token reads, scalar weight tile ----------------
// dyn smem floats: bufA[256][TPAD] @0 | bufB[256][TPAD] @256*TPAD | Wt[32][257] @2*256*TPAD
#define MLP_SMEM ((2 * 256 * TPAD + 32 * 257) * 4)

template<int TP>
__device__ __forceinline__ void run_layer_t(const float* __restrict__ Wg, float bj,
                                            const float* __restrict__ bufIn,
                                            float* __restrict__ Wt,
                                            unsigned long long acc[TP / 2]) {
    int tid = threadIdx.x;
    unsigned long long binit = pk2(bj, bj);
    #pragma unroll
    for (int p = 0; p < TP / 2; p++) acc[p] = binit;
    for (int kc = 0; kc < 256; kc += 32) {
        // stage transposed weight chunk Wt[k][j] = W[j][kc+k]
        #pragma unroll
        for (int r = 0; r < 8; r++) {
            int e = (r * 256 + tid) * 4;
            int j2 = e >> 5, i = e & 31;
            float4 w4 = *reinterpret_cast<const float4*>(Wg + j2 * 256 + kc + i);
            Wt[(i + 0) * 257 + j2] = w4.x;
            Wt[(i + 1) * 257 + j2] = w4.y;
            Wt[(i + 2) * 257 + j2] = w4.z;
            Wt[(i + 3) * 257 + j2] = w4.w;
        }
        __syncthreads();
        #pragma unroll 8
        for (int k = 0; k < 32; k++) {
            float w = Wt[k * 257 + tid];
            unsigned long long wd = pk2(w, w);
            const ulonglong2* tv = reinterpret_cast<const ulonglong2*>(bufIn + (kc + k) * TPAD);
            #pragma unroll
            for (int p = 0; p < TP / 4; p++) {
                ulonglong2 q = tv[p];
                acc[2 * p]     = fma2(q.x, wd, acc[2 * p]);
                acc[2 * p + 1] = fma2(q.y, wd, acc[2 * p + 1]);
            }
        }
        __syncthreads();
    }
}

template<int TP>
__global__ void __launch_bounds__(256) mlp_kernel_t(
    const float* __restrict__ x, const float* __restrict__ pe,
    const float* __restrict__ W1, const float* __restrict__ B1,
    const float* __restrict__ W2, const float* __restrict__ B2,
    const float* __restrict__ W3, const float* __restrict__ B3,
    const float* __restrict__ qv, float* __restrict__ outp, int kq) {
    extern __shared__ float sh[];
    float* bufA = sh;
    float* bufB = sh + 256 * TPAD;
    float* Wt   = sh + 2 * 256 * TPAD;
    int tid = threadIdx.x;
    int blk = blockIdx.x;

    // gather feat rows: x[b][c][idx] + bilinear(pe[c]) at idx, k-major bufA[c][t]
    #pragma unroll
    for (int t = 0; t < TP; t++) {
        int g = blk * TP + t;
        int b = g / kq, qi = g % kq;
        int idx = g_idx[b * KDET + qi];
        int yy = idx / 100, xx = idx % 100;
        float sy = (yy + 0.5f) * 0.5f - 0.5f; sy = fminf(fmaxf(sy, 0.f), 49.f);
        int y0 = (int)floorf(sy); int y1 = min(y0 + 1, 49); float ty = sy - (float)y0;
        float sx = (xx + 0.5f) * 0.5f - 0.5f; sx = fminf(fmaxf(sx, 0.f), 49.f);
        int x0 = (int)floorf(sx); int x1 = min(x0 + 1, 49); float tx = sx - (float)x0;
        const float* pc = pe + (size_t)tid * 2500;
        float v00 = __ldg(pc + y0 * 50 + x0), v01 = __ldg(pc + y0 * 50 + x1);
        float v10 = __ldg(pc + y1 * 50 + x0), v11 = __ldg(pc + y1 * 50 + x1);
        float r0 = v00 * (1.f - ty) + v10 * ty;
        float r1 = v01 * (1.f - ty) + v11 * ty;
        float pos = r0 * (1.f - tx) + r1 * tx;
        float xv = __ldg(x + ((size_t)(b * CDIM + tid)) * NPIX + idx);
        bufA[tid * TPAD + t] = xv + pos;
    }
    __syncthreads();

    unsigned long long acc[TP / 2];
    run_layer_t<TP>(W1, B1[tid], bufA, Wt, acc);
    #pragma unroll
    for (int p = 0; p < TP / 2; p++) {
        float u, v; upk2(acc[p], u, v);
        *reinterpret_cast<unsigned long long*>(&bufB[tid * TPAD + 2 * p]) =
            pk2(fmaxf(u, 0.f), fmaxf(v, 0.f));
    }
    __syncthreads();

    run_layer_t<TP>(W2, B2[tid], bufB, Wt, acc);
    #pragma unroll
    for (int p = 0; p < TP / 2; p++) {
        float u, v; upk2(acc[p], u, v);
        *reinterpret_cast<unsigned long long*>(&bufA[tid * TPAD + 2 * p]) =
            pk2(fmaxf(u, 0.f), fmaxf(v, 0.f));
    }
    __syncthreads();

    run_layer_t<TP>(W3, B3[tid], bufA, Wt, acc);
    #pragma unroll
    for (int p = 0; p < TP / 2; p++) {
        float u, v; upk2(acc[p], u, v);
        int g0 = blk * TP + 2 * p;
        int qi0 = g0 % kq, qi1 = (g0 + 1) % kq;
        outp[(size_t)g0 * 256 + tid]       = u + qv[qi0 * 256 + tid];
        outp[(size_t)(g0 + 1) * 256 + tid] = v + qv[qi1 * 256 + tid];
    }
}

// ---------------- launch ----------------
extern "C" void kernel_launch(void* const* d_in, const int* in_sizes, int n_in,
                              void* d_out, int out_size) {
    const float* x     = (const float*)d_in[0];
    const float* Wc    = (const float*)d_in[1];
    const float* bc    = (const float*)d_in[2];
    const float* Wb    = (const float*)d_in[3];
    const float* bb    = (const float*)d_in[4];
    const float* dW1   = (const float*)d_in[5];
    const float* db1   = (const float*)d_in[6];
    const float* dW2   = (const float*)d_in[7];
    const float* db2   = (const float*)d_in[8];
    const float* dW3   = (const float*)d_in[9];
    const float* db3   = (const float*)d_in[10];
    const float* rW1   = (const float*)d_in[11];
    const float* rb1   = (const float*)d_in[12];
    const float* rW2   = (const float*)d_in[13];
    const float* rb2   = (const float*)d_in[14];
    const float* rW3   = (const float*)d_in[15];
    const float* rb3   = (const float*)d_in[16];
    const float* det_q = (const float*)d_in[17];
    const float* rec_q = (const float*)d_in[18];
    const float* pe    = (const float*)d_in[19];

    float* out = (float*)d_out;
    float* out_det = out;               // 16*100*256 = 409600
    float* out_rec = out + 409600;      // 16*25*256  = 102400
    float* out_cls = out + 512000;      // 16*10000*2 = 320000
    float* out_bb  = out + 832000;      // 16*10000*4 = 640000

    pos_proj_part_kernel<<<(PPARTS * 2500 + 255) / 256, 256>>>(pe, Wc, Wb);
    pos_proj_reduce_kernel<<<(6 * 2500 + 255) / 256, 256>>>();
    resize6_kernel<<<(6 * NPIX + 255) / 256, 256>>>();

    main_pass_kernel<<<625, 128>>>(x, bc, bb, Wc, Wb, out_cls, out_bb);

    cudaFuncSetAttribute(topk_kernel, cudaFuncAttributeMaxDynamicSharedMemorySize, TK_SMEM);
    topk_kernel<<<BATCH, 1024, TK_SMEM>>>();

    cudaFuncSetAttribute(mlp_kernel_t<16>, cudaFuncAttributeMaxDynamicSharedMemorySize, MLP_SMEM);
    cudaFuncSetAttribute(mlp_kernel_t<8>, cudaFuncAttributeMaxDynamicSharedMemorySize, MLP_SMEM);
    // det: 1600 tokens / 16 = 100 blocks; rec: 400 tokens / 8 = 50 blocks (independent; co-schedule)
    mlp_kernel_t<16><<<100, 256, MLP_SMEM>>>(x, pe, dW1, db1, dW2, db2, dW3, db3,
                                             det_q, out_det, KDET);
    mlp_kernel_t<8><<<50, 256, MLP_SMEM>>>(x, pe, rW1, rb1, rW2, rb2, rW3, rb3,
                                           rec_q, out_rec, KREC);
}

// round 6
// speedup vs baseline: 1.2958x; 1.2958x over previous
#include <cuda_runtime.h>
#include <cstdint>

#define BATCH 16
#define CDIM 256
#define NPIX 10000
#define KDET 100
#define KREC 25
#define TPAD 20
#define PPARTS 8

// ---------------- scratch (static device globals) ----------------
__device__ float g_ppq[PPARTS * 6 * 2500];   // partial projections of pe (50x50 grid)
__device__ float g_pq[6 * 2500];             // pos projections on 50x50 grid
__device__ float g_pp[6 * NPIX];             // resized pos projections [6, N]
__device__ unsigned g_keys[BATCH * NPIX];    // monotone-transformed margin keys
__device__ int g_idx[BATCH * KDET];          // top-100 indices per batch
__device__ float g_feat[BATCH * KDET * CDIM]; // gathered x+pos for selected tokens

// ---------------- f32x2 packed helpers ----------------
__device__ __forceinline__ unsigned long long pk2(float a, float b) {
    unsigned long long r;
    asm("mov.b64 %0, {%1,%2};" : "=l"(r) : "f"(a), "f"(b));
    return r;
}
__device__ __forceinline__ void upk2(unsigned long long v, float& a, float& b) {
    asm("mov.b64 {%0,%1}, %2;" : "=f"(a), "=f"(b) : "l"(v));
}
__device__ __forceinline__ unsigned long long fma2(unsigned long long a, unsigned long long b, unsigned long long c) {
    unsigned long long d;
    asm("fma.rn.f32x2 %0, %1, %2, %3;" : "=l"(d) : "l"(a), "l"(b), "l"(c));
    return d;
}
__device__ __forceinline__ unsigned key_xform(float f) {
    unsigned u = __float_as_uint(f);
    return (u & 0x80000000u) ? ~u : (u | 0x80000000u);
}

// ---------------- P1: project pe (256ch, 50x50) onto 6 weight rows, split over C ----------------
__global__ void pos_proj_part_kernel(const float* __restrict__ pe,
                                     const float* __restrict__ Wc, const float* __restrict__ Wb) {
    __shared__ float ws[6 * 256];
    int tid = threadIdx.x;
    for (int i = tid; i < 512; i += blockDim.x) ws[i] = Wc[i];
    for (int i = tid; i < 1024; i += blockDim.x) ws[512 + i] = Wb[i];
    __syncthreads();
    int id = blockIdx.x * blockDim.x + tid;
    if (id >= PPARTS * 2500) return;
    int part = id / 2500, pix = id % 2500;
    int c0 = part * 32;
    float a0 = 0, a1 = 0, a2 = 0, a3 = 0, a4 = 0, a5 = 0;
    #pragma unroll 8
    for (int i = 0; i < 32; i++) {
        int c = c0 + i;
        float p = __ldg(pe + (size_t)c * 2500 + pix);
        a0 += p * ws[c];        a1 += p * ws[256 + c];
        a2 += p * ws[512 + c];  a3 += p * ws[768 + c];
        a4 += p * ws[1024 + c]; a5 += p * ws[1280 + c];
    }
    float* o = g_ppq + (size_t)part * 6 * 2500 + pix;
    o[0] = a0; o[2500] = a1; o[5000] = a2; o[7500] = a3; o[10000] = a4; o[12500] = a5;
}

// ---------------- P2: reduce 8 partials ----------------
__global__ void pos_proj_reduce_kernel() {
    int id = blockIdx.x * blockDim.x + threadIdx.x;
    if (id >= 6 * 2500) return;
    float s = 0.f;
    #pragma unroll
    for (int p = 0; p < PPARTS; p++) s += g_ppq[(size_t)p * 6 * 2500 + id];
    g_pq[id] = s;
}

// ---------------- P3: bilinear resize the 6 projected channels 50x50 -> 100x100 ----------------
__global__ void resize6_kernel() {
    int id = blockIdx.x * blockDim.x + threadIdx.x;
    if (id >= 6 * NPIX) return;
    int w = id / NPIX, n = id % NPIX;
    int y = n / 100, x = n % 100;
    float sy = (y + 0.5f) * 0.5f - 0.5f; sy = fminf(fmaxf(sy, 0.f), 49.f);
    int y0 = (int)floorf(sy); int y1 = min(y0 + 1, 49); float ty = sy - (float)y0;
    float sx = (x + 0.5f) * 0.5f - 0.5f; sx = fminf(fmaxf(sx, 0.f), 49.f);
    int x0 = (int)floorf(sx); int x1 = min(x0 + 1, 49); float tx = sx - (float)x0;
    const float* p = g_pq + (size_t)w * 2500;
    float v00 = p[y0 * 50 + x0], v01 = p[y0 * 50 + x1];
    float v10 = p[y1 * 50 + x0], v11 = p[y1 * 50 + x1];
    float r0 = v00 * (1.f - ty) + v10 * ty;
    float r1 = v01 * (1.f - ty) + v11 * ty;
    g_pp[(size_t)w * NPIX + n] = r0 * (1.f - tx) + r1 * tx;
}

// ---------------- B: stream x once, 2px/thread f32x2, double-buffered prefetch ----------------
__global__ void __launch_bounds__(128) main_pass_kernel(
        const float* __restrict__ x,
        const float* __restrict__ bc, const float* __restrict__ bb,
        const float* __restrict__ Wc, const float* __restrict__ Wb,
        float* __restrict__ out_cls, float* __restrict__ out_bb) {
    __shared__ unsigned long long ws2[6 * 256];   // duplicated (w,w) pairs, 12 KB
    int tid = threadIdx.x;
    for (int i = tid; i < 1536; i += 128) {
        float v = (i < 512) ? Wc[i] : Wb[i - 512];
        ws2[i] = pk2(v, v);
    }
    __syncthreads();
    int id = blockIdx.x * 128 + tid;        // 80000 items, 2px each
    int b = id / (NPIX / 2);
    int n2 = (id % (NPIX / 2)) * 2;
    const float* base = x + (size_t)b * CDIM * NPIX + n2;
    unsigned long long acc0 = 0, acc1 = 0, acc2 = 0, acc3 = 0, acc4 = 0, acc5 = 0;
    unsigned long long A[8], B[8];
    #pragma unroll
    for (int i = 0; i < 8; i++)
        A[i] = __ldg(reinterpret_cast<const unsigned long long*>(base + (size_t)i * NPIX));
    for (int c0 = 0; c0 < 256; c0 += 16) {
        #pragma unroll
        for (int i = 0; i < 8; i++)
            B[i] = __ldg(reinterpret_cast<const unsigned long long*>(base + (size_t)(c0 + 8 + i) * NPIX));
        #pragma unroll
        for (int i = 0; i < 8; i++) {
            int c = c0 + i;
            unsigned long long v = A[i];
            acc0 = fma2(v, ws2[c], acc0);
            acc1 = fma2(v, ws2[256 + c], acc1);
            acc2 = fma2(v, ws2[512 + c], acc2);
            acc3 = fma2(v, ws2[768 + c], acc3);
            acc4 = fma2(v, ws2[1024 + c], acc4);
            acc5 = fma2(v, ws2[1280 + c], acc5);
        }
        if (c0 + 16 < 256) {
            #pragma unroll
            for (int i = 0; i < 8; i++)
                A[i] = __ldg(reinterpret_cast<const unsigned long long*>(base + (size_t)(c0 + 16 + i) * NPIX));
        }
        #pragma unroll
        for (int i = 0; i < 8; i++) {
            int c = c0 + 8 + i;
            unsigned long long v = B[i];
            acc0 = fma2(v, ws2[c], acc0);
            acc1 = fma2(v, ws2[256 + c], acc1);
            acc2 = fma2(v, ws2[512 + c], acc2);
            acc3 = fma2(v, ws2[768 + c], acc3);
            acc4 = fma2(v, ws2[1024 + c], acc4);
            acc5 = fma2(v, ws2[1280 + c], acc5);
        }
    }
    float a0x, a0y, a1x, a1y, a2x, a2y, a3x, a3y, a4x, a4y, a5x, a5y;
    upk2(acc0, a0x, a0y); upk2(acc1, a1x, a1y); upk2(acc2, a2x, a2y);
    upk2(acc3, a3x, a3y); upk2(acc4, a4x, a4y); upk2(acc5, a5x, a5y);
    float2 p0 = *reinterpret_cast<const float2*>(g_pp + 0 * NPIX + n2);
    float2 p1 = *reinterpret_cast<const float2*>(g_pp + 1 * NPIX + n2);
    float2 p2 = *reinterpret_cast<const float2*>(g_pp + 2 * NPIX + n2);
    float2 p3 = *reinterpret_cast<const float2*>(g_pp + 3 * NPIX + n2);
    float2 p4 = *reinterpret_cast<const float2*>(g_pp + 4 * NPIX + n2);
    float2 p5 = *reinterpret_cast<const float2*>(g_pp + 5 * NPIX + n2);
    float bc0 = bc[0], bc1 = bc[1];
    float bb0 = bb[0], bb1 = bb[1], bb2 = bb[2], bb3 = bb[3];
    float l0x = a0x + p0.x + bc0, l0y = a0y + p0.y + bc0;
    float l1x = a1x + p1.x + bc1, l1y = a1y + p1.y + bc1;
    size_t co = ((size_t)b * NPIX + n2) * 2;
    *reinterpret_cast<float4*>(out_cls + co) = make_float4(l0x, l1x, l0y, l1y);
    size_t bo = ((size_t)b * NPIX + n2) * 4;
    *reinterpret_cast<float4*>(out_bb + bo) =
        make_float4(a2x + p2.x + bb0, a3x + p3.x + bb1, a4x + p4.x + bb2, a5x + p5.x + bb3);
    *reinterpret_cast<float4*>(out_bb + bo + 4) =
        make_float4(a2y + p2.y + bb0, a3y + p3.y + bb1, a4y + p4.y + bb2, a5y + p5.y + bb3);
    uint2 kk = make_uint2(key_xform(l1x - l0x), key_xform(l1y - l0y));
    *reinterpret_cast<uint2*>(g_keys + (size_t)b * NPIX + n2) = kk;
}

// ---------------- C: exact per-batch top-100 (value desc, index asc) ----------------
// dyn smem: cand[256] ull @0 | keys[NPIX] u32 @2048 | hist[2048] u32 @42048 | tot[257] u32 @50240
#define TK_SMEM (50240 + 260 * 4)
__global__ void __launch_bounds__(1024) topk_kernel() {
    extern __shared__ char sm[];
    unsigned long long* cand = reinterpret_cast<unsigned long long*>(sm);
    unsigned* keys = reinterpret_cast<unsigned*>(sm + 2048);
    unsigned* histv = reinterpret_cast<unsigned*>(sm + 42048);
    unsigned* tot = reinterpret_cast<unsigned*>(sm + 50240);
    __shared__ unsigned s_prefix;
    __shared__ int s_kk, s_cnt;
    int b = blockIdx.x, tid = threadIdx.x;

    for (int i = tid; i < NPIX; i += 1024) keys[i] = g_keys[(size_t)b * NPIX + i];
    if (tid == 0) { s_prefix = 0u; s_kk = KDET; s_cnt = 0; }
    __syncthreads();

    #pragma unroll
    for (int pass = 0; pass < 4; pass++) {
        int shift = 24 - 8 * pass;
        unsigned himask = (pass == 0) ? 0u : (0xFFFFFFFFu << (shift + 8));
        for (int i = tid; i < 2048; i += 1024) histv[i] = 0;
        __syncthreads();
        unsigned prefix = s_prefix;
        int kk = s_kk;
        unsigned* myh = histv + ((tid >> 5) & 7) * 256;
        for (int i = tid; i < NPIX; i += 1024) {
            unsigned u = keys[i];
            if (((u ^ prefix) & himask) == 0) atomicAdd(&myh[(u >> shift) & 255], 1u);
        }
        __syncthreads();
        if (tid < 256) {
            unsigned s = 0;
            #pragma unroll
            for (int cp = 0; cp < 8; cp++) s += histv[cp * 256 + tid];
            tot[tid] = s;
        }
        __syncthreads();
        #pragma unroll
        for (int step = 1; step < 256; step <<= 1) {
            unsigned v = 0;
            if (tid < 256) v = tot[tid] + ((tid + step < 256) ? tot[tid + step] : 0u);
            __syncthreads();
            if (tid < 256) tot[tid] = v;
            __syncthreads();
        }
        if (tid < 256) {
            unsigned Sb = tot[tid];
            unsigned Sb1 = (tid < 255) ? tot[tid + 1] : 0u;
            if (Sb >= (unsigned)kk && Sb1 < (unsigned)kk) {
                s_prefix = prefix | ((unsigned)tid << shift);
                s_kk = kk - (int)Sb1;
            }
        }
        __syncthreads();
    }
    unsigned T = s_prefix;

    for (int i = tid; i < NPIX; i += 1024) {
        unsigned u = keys[i];
        if (u >= T) {
            int p = atomicAdd(&s_cnt, 1);
            if (p < 256)
                cand[p] = ((unsigned long long)u << 32) | (unsigned)(~(unsigned)i);
        }
    }
    __syncthreads();
    int cnt = min(s_cnt, 256);
    for (int i = cnt + tid; i < 256; i += 1024) cand[i] = 0ull;
    __syncthreads();

    for (int ksz = 2; ksz <= 256; ksz <<= 1) {
        for (int j = ksz >> 1; j > 0; j >>= 1) {
            if (tid < 256) {
                int l = tid ^ j;
                if (l > tid) {
                    unsigned long long a = cand[tid], c2 = cand[l];
                    bool dirDesc = ((tid & ksz) == 0);
                    if ((a < c2) == dirDesc) { cand[tid] = c2; cand[l] = a; }
                }
            }
            __syncthreads();
        }
    }
    if (tid < KDET)
        g_idx[b * KDET + tid] = (int)(~((unsigned)(cand[tid] & 0xFFFFFFFFull)));
}

// ---------------- G: gather x+pos for the 1600 selected tokens (one block per token) ----------------
__global__ void __launch_bounds__(256) gather_kernel(const float* __restrict__ x,
                                                     const float* __restrict__ pe) {
    int g = blockIdx.x;           // 0..1599 : b = g/100, qi = g%100
    int tid = threadIdx.x;        // channel
    int idx = g_idx[g];
    int yy = idx / 100, xx = idx % 100;
    float sy = (yy + 0.5f) * 0.5f - 0.5f; sy = fminf(fmaxf(sy, 0.f), 49.f);
    int y0 = (int)floorf(sy); int y1 = min(y0 + 1, 49); float ty = sy - (float)y0;
    float sx = (xx + 0.5f) * 0.5f - 0.5f; sx = fminf(fmaxf(sx, 0.f), 49.f);
    int x0 = (int)floorf(sx); int x1 = min(x0 + 1, 49); float tx = sx - (float)x0;
    const float* pc = pe + (size_t)tid * 2500;
    float v00 = __ldg(pc + y0 * 50 + x0), v01 = __ldg(pc + y0 * 50 + x1);
    float v10 = __ldg(pc + y1 * 50 + x0), v11 = __ldg(pc + y1 * 50 + x1);
    float r0 = v00 * (1.f - ty) + v10 * ty;
    float r1 = v01 * (1.f - ty) + v11 * ty;
    float pos = r0 * (1.f - tx) + r1 * tx;
    int b = g / KDET;
    float xv = __ldg(x + ((size_t)(b * CDIM + tid)) * NPIX + idx);
    g_feat[(size_t)g * CDIM + tid] = xv + pos;
}

// ---------------- MLP: f32x2 token pairs, LDS.128 token reads, scalar weight tile ----------------
// dyn smem floats: bufA[256][TPAD] @0 | bufB[256][TPAD] @256*TPAD | Wt[32][257] @2*256*TPAD
#define MLP_SMEM ((2 * 256 * TPAD + 32 * 257) * 4)

template<int TP>
__device__ __forceinline__ void run_layer_t(const float* __restrict__ Wg, float bj,
                                            const float* __restrict__ bufIn,
                                            float* __restrict__ Wt,
                                            unsigned long long acc[TP / 2]) {
    int tid = threadIdx.x;
    unsigned long long binit = pk2(bj, bj);
    #pragma unroll
    for (int p = 0; p < TP / 2; p++) acc[p] = binit;
    for (int kc = 0; kc < 256; kc += 32) {
        // stage transposed weight chunk Wt[k][j] = W[j][kc+k]
        #pragma unroll
        for (int r = 0; r < 8; r++) {
            int e = (r * 256 + tid) * 4;
            int j2 = e >> 5, i = e & 31;
            float4 w4 = *reinterpret_cast<const float4*>(Wg + j2 * 256 + kc + i);
            Wt[(i + 0) * 257 + j2] = w4.x;
            Wt[(i + 1) * 257 + j2] = w4.y;
            Wt[(i + 2) * 257 + j2] = w4.z;
            Wt[(i + 3) * 257 + j2] = w4.w;
        }
        __syncthreads();
        #pragma unroll 8
        for (int k = 0; k < 32; k++) {
            float w = Wt[k * 257 + tid];
            unsigned long long wd = pk2(w, w);
            const ulonglong2* tv = reinterpret_cast<const ulonglong2*>(bufIn + (kc + k) * TPAD);
            #pragma unroll
            for (int p = 0; p < TP / 4; p++) {
                ulonglong2 q = tv[p];
                acc[2 * p]     = fma2(q.x, wd, acc[2 * p]);
                acc[2 * p + 1] = fma2(q.y, wd, acc[2 * p + 1]);
            }
        }
        __syncthreads();
    }
}

template<int TP, int KQ>
__global__ void __launch_bounds__(256) mlp_kernel_t(
    const float* __restrict__ W1, const float* __restrict__ B1,
    const float* __restrict__ W2, const float* __restrict__ B2,
    const float* __restrict__ W3, const float* __restrict__ B3,
    const float* __restrict__ qv, float* __restrict__ outp) {
    extern __shared__ float sh[];
    float* bufA = sh;
    float* bufB = sh + 256 * TPAD;
    float* Wt   = sh + 2 * 256 * TPAD;
    int tid = threadIdx.x;
    int blk = blockIdx.x;

    // coalesced gather from g_feat (k-major: bufA[c][t])
    #pragma unroll
    for (int t = 0; t < TP; t++) {
        int g = blk * TP + t;
        int row = (KQ == KDET) ? g : ((g / KREC) * KDET + (g % KREC));
        bufA[tid * TPAD + t] = g_feat[(size_t)row * CDIM + tid];
    }
    __syncthreads();

    unsigned long long acc[TP / 2];
    run_layer_t<TP>(W1, B1[tid], bufA, Wt, acc);
    #pragma unroll
    for (int p = 0; p < TP / 2; p++) {
        float u, v; upk2(acc[p], u, v);
        *reinterpret_cast<unsigned long long*>(&bufB[tid * TPAD + 2 * p]) =
            pk2(fmaxf(u, 0.f), fmaxf(v, 0.f));
    }
    __syncthreads();

    run_layer_t<TP>(W2, B2[tid], bufB, Wt, acc);
    #pragma unroll
    for (int p = 0; p < TP / 2; p++) {
        float u, v; upk2(acc[p], u, v);
        *reinterpret_cast<unsigned long long*>(&bufA[tid * TPAD + 2 * p]) =
            pk2(fmaxf(u, 0.f), fmaxf(v, 0.f));
    }
    __syncthreads();

    run_layer_t<TP>(W3, B3[tid], bufA, Wt, acc);
    #pragma unroll
    for (int p = 0; p < TP / 2; p++) {
        float u, v; upk2(acc[p], u, v);
        int g0 = blk * TP + 2 * p;
        int qi0 = g0 % KQ, qi1 = (g0 + 1) % KQ;
        outp[(size_t)g0 * 256 + tid]       = u + qv[qi0 * 256 + tid];
        outp[(size_t)(g0 + 1) * 256 + tid] = v + qv[qi1 * 256 + tid];
    }
}

// ---------------- launch ----------------
extern "C" void kernel_launch(void* const* d_in, const int* in_sizes, int n_in,
                              void* d_out, int out_size) {
    const float* x     = (const float*)d_in[0];
    const float* Wc    = (const float*)d_in[1];
    const float* bc    = (const float*)d_in[2];
    const float* Wb    = (const float*)d_in[3];
    const float* bb    = (const float*)d_in[4];
    const float* dW1   = (const float*)d_in[5];
    const float* db1   = (const float*)d_in[6];
    const float* dW2   = (const float*)d_in[7];
    const float* db2   = (const float*)d_in[8];
    const float* dW3   = (const float*)d_in[9];
    const float* db3   = (const float*)d_in[10];
    const float* rW1   = (const float*)d_in[11];
    const float* rb1   = (const float*)d_in[12];
    const float* rW2   = (const float*)d_in[13];
    const float* rb2   = (const float*)d_in[14];
    const float* rW3   = (const float*)d_in[15];
    const float* rb3   = (const float*)d_in[16];
    const float* det_q = (const float*)d_in[17];
    const float* rec_q = (const float*)d_in[18];
    const float* pe    = (const float*)d_in[19];

    float* out = (float*)d_out;
    float* out_det = out;               // 16*100*256 = 409600
    float* out_rec = out + 409600;      // 16*25*256  = 102400
    float* out_cls = out + 512000;      // 16*10000*2 = 320000
    float* out_bb  = out + 832000;      // 16*10000*4 = 640000

    pos_proj_part_kernel<<<(PPARTS * 2500 + 255) / 256, 256>>>(pe, Wc, Wb);
    pos_proj_reduce_kernel<<<(6 * 2500 + 255) / 256, 256>>>();
    resize6_kernel<<<(6 * NPIX + 255) / 256, 256>>>();

    main_pass_kernel<<<625, 128>>>(x, bc, bb, Wc, Wb, out_cls, out_bb);

    cudaFuncSetAttribute(topk_kernel, cudaFuncAttributeMaxDynamicSharedMemorySize, TK_SMEM);
    topk_kernel<<<BATCH, 1024, TK_SMEM>>>();

    gather_kernel<<<BATCH * KDET, 256>>>(x, pe);

    cudaFuncSetAttribute(mlp_kernel_t<16, KDET>, cudaFuncAttributeMaxDynamicSharedMemorySize, MLP_SMEM);
    cudaFuncSetAttribute(mlp_kernel_t<8, KREC>, cudaFuncAttributeMaxDynamicSharedMemorySize, MLP_SMEM);
    // det: 1600 tokens / 16 = 100 blocks; rec: 400 tokens / 8 = 50 blocks (independent; co-schedule)
    mlp_kernel_t<16, KDET><<<100, 256, MLP_SMEM>>>(dW1, db1, dW2, db2, dW3, db3, det_q, out_det);
    mlp_kernel_t<8, KREC><<<50, 256, MLP_SMEM>>>(rW1, rb1, rW2, rb2, rW3, rb3, rec_q, out_rec);
}

// round 8
// speedup vs baseline: 1.2969x; 1.0009x over previous
#include <cuda_runtime.h>
#include <cstdint>

#define BATCH 16
#define CDIM 256
#define NPIX 10000
#define KDET 100
#define KREC 25
#define TPAD 12
#define PPARTS 8

// ---------------- scratch (static device globals) ----------------
__device__ float g_ppq[PPARTS * 6 * 2500];   // partial projections of pe (50x50 grid)
__device__ float g_pq[6 * 2500];             // pos projections on 50x50 grid
__device__ unsigned g_keys[BATCH * NPIX];    // monotone-transformed margin keys
__device__ int g_idx[BATCH * KDET];          // top-100 indices per batch
__device__ float g_feat[BATCH * KDET * CDIM]; // gathered x+pos for selected tokens

// ---------------- f32x2 packed helpers ----------------
__device__ __forceinline__ unsigned long long pk2(float a, float b) {
    unsigned long long r;
    asm("mov.b64 %0, {%1,%2};" : "=l"(r) : "f"(a), "f"(b));
    return r;
}
__device__ __forceinline__ void upk2(unsigned long long v, float& a, float& b) {
    asm("mov.b64 {%0,%1}, %2;" : "=f"(a), "=f"(b) : "l"(v));
}
__device__ __forceinline__ unsigned long long fma2(unsigned long long a, unsigned long long b, unsigned long long c) {
    unsigned long long d;
    asm("fma.rn.f32x2 %0, %1, %2, %3;" : "=l"(d) : "l"(a), "l"(b), "l"(c));
    return d;
}
__device__ __forceinline__ unsigned key_xform(float f) {
    unsigned u = __float_as_uint(f);
    return (u & 0x80000000u) ? ~u : (u | 0x80000000u);
}
// bilinear coefficients for 50->100 upsample at output coord n (0..99)
__device__ __forceinline__ void bil_coord(int o, int& i0, int& i1, float& t) {
    float s = (o + 0.5f) * 0.5f - 0.5f; s = fminf(fmaxf(s, 0.f), 49.f);
    i0 = (int)floorf(s); i1 = min(i0 + 1, 49); t = s - (float)i0;
}

// ---------------- P1: project pe (256ch, 50x50) onto 6 weight rows, split over C ----------------
__global__ void pos_proj_part_kernel(const float* __restrict__ pe,
                                     const float* __restrict__ Wc, const float* __restrict__ Wb) {
    __shared__ float ws[6 * 256];
    int tid = threadIdx.x;
    for (int i = tid; i < 512; i += blockDim.x) ws[i] = Wc[i];
    for (int i = tid; i < 1024; i += blockDim.x) ws[512 + i] = Wb[i];
    __syncthreads();
    int id = blockIdx.x * blockDim.x + tid;
    if (id >= PPARTS * 2500) return;
    int part = id / 2500, pix = id % 2500;
    int c0 = part * 32;
    float a0 = 0, a1 = 0, a2 = 0, a3 = 0, a4 = 0, a5 = 0;
    #pragma unroll 8
    for (int i = 0; i < 32; i++) {
        int c = c0 + i;
        float p = __ldg(pe + (size_t)c * 2500 + pix);
        a0 += p * ws[c];        a1 += p * ws[256 + c];
        a2 += p * ws[512 + c];  a3 += p * ws[768 + c];
        a4 += p * ws[1024 + c]; a5 += p * ws[1280 + c];
    }
    float* o = g_ppq + (size_t)part * 6 * 2500 + pix;
    o[0] = a0; o[2500] = a1; o[5000] = a2; o[7500] = a3; o[10000] = a4; o[12500] = a5;
}

// ---------------- P2: reduce 8 partials ----------------
__global__ void pos_proj_reduce_kernel() {
    int id = blockIdx.x * blockDim.x + threadIdx.x;
    if (id >= 6 * 2500) return;
    float s = 0.f;
    #pragma unroll
    for (int p = 0; p < PPARTS; p++) s += g_ppq[(size_t)p * 6 * 2500 + id];
    g_pq[id] = s;
}

// ---------------- B: stream x once, 2px/thread f32x2, depth-16 double buffer; inline pos bilerp ----
__global__ void __launch_bounds__(128, 4) main_pass_kernel(
        const float* __restrict__ x,
        const float* __restrict__ bc, const float* __restrict__ bb,
        const float* __restrict__ Wc, const float* __restrict__ Wb,
        float* __restrict__ out_cls, float* __restrict__ out_bb) {
    __shared__ unsigned long long ws2[6 * 256];   // duplicated (w,w) pairs, 12 KB
    int tid = threadIdx.x;
    for (int i = tid; i < 1536; i += 128) {
        float v = (i < 512) ? Wc[i] : Wb[i - 512];
        ws2[i] = pk2(v, v);
    }
    __syncthreads();
    int id = blockIdx.x * 128 + tid;        // 80000 items, 2px each
    int b = id / (NPIX / 2);
    int n2 = (id % (NPIX / 2)) * 2;
    const float* base = x + (size_t)b * CDIM * NPIX + n2;
    unsigned long long acc0 = 0, acc1 = 0, acc2 = 0, acc3 = 0, acc4 = 0, acc5 = 0;
    unsigned long long A[16], B[16];
    #pragma unroll
    for (int i = 0; i < 16; i++)
        A[i] = __ldg(reinterpret_cast<const unsigned long long*>(base + (size_t)i * NPIX));
    for (int c0 = 0; c0 < 256; c0 += 32) {
        #pragma unroll
        for (int i = 0; i < 16; i++)
            B[i] = __ldg(reinterpret_cast<const unsigned long long*>(base + (size_t)(c0 + 16 + i) * NPIX));
        #pragma unroll
        for (int i = 0; i < 16; i++) {
            int c = c0 + i;
            unsigned long long v = A[i];
            acc0 = fma2(v, ws2[c], acc0);
            acc1 = fma2(v, ws2[256 + c], acc1);
            acc2 = fma2(v, ws2[512 + c], acc2);
            acc3 = fma2(v, ws2[768 + c], acc3);
            acc4 = fma2(v, ws2[1024 + c], acc4);
            acc5 = fma2(v, ws2[1280 + c], acc5);
        }
        if (c0 + 32 < 256) {
            #pragma unroll
            for (int i = 0; i < 16; i++)
                A[i] = __ldg(reinterpret_cast<const unsigned long long*>(base + (size_t)(c0 + 32 + i) * NPIX));
        }
        #pragma unroll
        for (int i = 0; i < 16; i++) {
            int c = c0 + 16 + i;
            unsigned long long v = B[i];
            acc0 = fma2(v, ws2[c], acc0);
            acc1 = fma2(v, ws2[256 + c], acc1);
            acc2 = fma2(v, ws2[512 + c], acc2);
            acc3 = fma2(v, ws2[768 + c], acc3);
            acc4 = fma2(v, ws2[1024 + c], acc4);
            acc5 = fma2(v, ws2[1280 + c], acc5);
        }
    }
    float a0x, a0y, a1x, a1y, a2x, a2y, a3x, a3y, a4x, a4y, a5x, a5y;
    upk2(acc0, a0x, a0y); upk2(acc1, a1x, a1y); upk2(acc2, a2x, a2y);
    upk2(acc3, a3x, a3y); upk2(acc4, a4x, a4y); upk2(acc5, a5x, a5y);

    // inline bilinear of the 6 projected pos channels at pixels n2, n2+1 (same row)
    int yy = n2 / 100, xxa = n2 % 100;
    int y0, y1, x0a, x1a, x0b, x1b; float ty, txa, txb;
    bil_coord(yy, y0, y1, ty);
    bil_coord(xxa, x0a, x1a, txa);
    bil_coord(xxa + 1, x0b, x1b, txb);
    float pA[6], pB[6];
    #pragma unroll
    for (int w = 0; w < 6; w++) {
        const float* p = g_pq + (size_t)w * 2500;
        float r0a = p[y0 * 50 + x0a] * (1.f - txa) + p[y0 * 50 + x1a] * txa;
        float r1a = p[y1 * 50 + x0a] * (1.f - txa) + p[y1 * 50 + x1a] * txa;
        pA[w] = r0a * (1.f - ty) + r1a * ty;
        float r0b = p[y0 * 50 + x0b] * (1.f - txb) + p[y0 * 50 + x1b] * txb;
        float r1b = p[y1 * 50 + x0b] * (1.f - txb) + p[y1 * 50 + x1b] * txb;
        pB[w] = r0b * (1.f - ty) + r1b * ty;
    }
    float bc0 = bc[0], bc1 = bc[1];
    float bb0 = bb[0], bb1 = bb[1], bb2 = bb[2], bb3 = bb[3];
    float l0x = a0x + pA[0] + bc0, l0y = a0y + pB[0] + bc0;
    float l1x = a1x + pA[1] + bc1, l1y = a1y + pB[1] + bc1;
    size_t co = ((size_t)b * NPIX + n2) * 2;
    *reinterpret_cast<float4*>(out_cls + co) = make_float4(l0x, l1x, l0y, l1y);
    size_t bo = ((size_t)b * NPIX + n2) * 4;
    *reinterpret_cast<float4*>(out_bb + bo) =
        make_float4(a2x + pA[2] + bb0, a3x + pA[3] + bb1, a4x + pA[4] + bb2, a5x + pA[5] + bb3);
    *reinterpret_cast<float4*>(out_bb + bo + 4) =
        make_float4(a2y + pB[2] + bb0, a3y + pB[3] + bb1, a4y + pB[4] + bb2, a5y + pB[5] + bb3);
    uint2 kk = make_uint2(key_xform(l1x - l0x), key_xform(l1y - l0y));
    *reinterpret_cast<uint2*>(g_keys + (size_t)b * NPIX + n2) = kk;
}

// ---------------- C: exact per-batch top-100 (value desc, index asc) ----------------
// dyn smem: cand[256] ull @0 | keys[NPIX] u32 @2048 | hist[2048] u32 @42048 | tot[257] u32 @50240
#define TK_SMEM (50240 + 260 * 4)
__global__ void __launch_bounds__(1024) topk_kernel() {
    extern __shared__ char sm[];
    unsigned long long* cand = reinterpret_cast<unsigned long long*>(sm);
    unsigned* keys = reinterpret_cast<unsigned*>(sm + 2048);
    unsigned* histv = reinterpret_cast<unsigned*>(sm + 42048);
    unsigned* tot = reinterpret_cast<unsigned*>(sm + 50240);
    __shared__ unsigned s_prefix;
    __shared__ int s_kk, s_cnt;
    int b = blockIdx.x, tid = threadIdx.x;

    for (int i = tid; i < NPIX; i += 1024) keys[i] = g_keys[(size_t)b * NPIX + i];
    if (tid == 0) { s_prefix = 0u; s_kk = KDET; s_cnt = 0; }
    __syncthreads();

    #pragma unroll
    for (int pass = 0; pass < 4; pass++) {
        int shift = 24 - 8 * pass;
        unsigned himask = (pass == 0) ? 0u : (0xFFFFFFFFu << (shift + 8));
        for (int i = tid; i < 2048; i += 1024) histv[i] = 0;
        __syncthreads();
        unsigned prefix = s_prefix;
        int kk = s_kk;
        unsigned* myh = histv + ((tid >> 5) & 7) * 256;
        for (int i = tid; i < NPIX; i += 1024) {
            unsigned u = keys[i];
            if (((u ^ prefix) & himask) == 0) atomicAdd(&myh[(u >> shift) & 255], 1u);
        }
        __syncthreads();
        if (tid < 256) {
            unsigned s = 0;
            #pragma unroll
            for (int cp = 0; cp < 8; cp++) s += histv[cp * 256 + tid];
            tot[tid] = s;
        }
        __syncthreads();
        // warp 0: suffix scan of 256 bins via shfl (lane l owns bins l*8..l*8+7)
        if (tid < 32) {
            unsigned v[8], gs = 0;
            #pragma unroll
            for (int i = 0; i < 8; i++) { v[i] = tot[tid * 8 + i]; gs += v[i]; }
            unsigned s = gs;
            #pragma unroll
            for (int off = 1; off < 32; off <<= 1) {
                unsigned t = __shfl_down_sync(0xFFFFFFFFu, s, off);
                if (tid + off < 32) s += t;
            }
            unsigned run = s - gs;   // sum of groups strictly above
            unsigned cum = 0;
            #pragma unroll
            for (int i = 7; i >= 0; i--) {
                cum += v[i];
                tot[tid * 8 + i] = cum + run;
            }
        }
        __syncthreads();
        if (tid < 256) {
            unsigned Sb = tot[tid];
            unsigned Sb1 = (tid < 255) ? tot[tid + 1] : 0u;
            if (Sb >= (unsigned)kk && Sb1 < (unsigned)kk) {
                s_prefix = prefix | ((unsigned)tid << shift);
                s_kk = kk - (int)Sb1;
            }
        }
        __syncthreads();
    }
    unsigned T = s_prefix;

    for (int i = tid; i < NPIX; i += 1024) {
        unsigned u = keys[i];
        if (u >= T) {
            int p = atomicAdd(&s_cnt, 1);
            if (p < 256)
                cand[p] = ((unsigned long long)u << 32) | (unsigned)(~(unsigned)i);
        }
    }
    __syncthreads();
    int cnt = min(s_cnt, 256);
    for (int i = cnt + tid; i < 256; i += 1024) cand[i] = 0ull;
    __syncthreads();

    for (int ksz = 2; ksz <= 256; ksz <<= 1) {
        for (int j = ksz >> 1; j > 0; j >>= 1) {
            if (tid < 256) {
                int l = tid ^ j;
                if (l > tid) {
                    unsigned long long a = cand[tid], c2 = cand[l];
                    bool dirDesc = ((tid & ksz) == 0);
                    if ((a < c2) == dirDesc) { cand[tid] = c2; cand[l] = a; }
                }
            }
            __syncthreads();
        }
    }
    if (tid < KDET)
        g_idx[b * KDET + tid] = (int)(~((unsigned)(cand[tid] & 0xFFFFFFFFull)));
}

// ---------------- G: gather x+pos for the 1600 selected tokens (one block per token) ----------------
__global__ void __launch_bounds__(256) gather_kernel(const float* __restrict__ x,
                                                     const float* __restrict__ pe) {
    int g = blockIdx.x;           // 0..1599 : b = g/100, qi = g%100
    int tid = threadIdx.x;        // channel
    int idx = g_idx[g];
    int yy = idx / 100, xx = idx % 100;
    int y0, y1, x0, x1; float ty, tx;
    bil_coord(yy, y0, y1, ty);
    bil_coord(xx, x0, x1, tx);
    const float* pc = pe + (size_t)tid * 2500;
    float v00 = __ldg(pc + y0 * 50 + x0), v01 = __ldg(pc + y0 * 50 + x1);
    float v10 = __ldg(pc + y1 * 50 + x0), v11 = __ldg(pc + y1 * 50 + x1);
    float r0 = v00 * (1.f - ty) + v10 * ty;
    float r1 = v01 * (1.f - ty) + v11 * ty;
    float pos = r0 * (1.f - tx) + r1 * tx;
    int b = g / KDET;
    float xv = __ldg(x + ((size_t)(b * CDIM + tid)) * NPIX + idx);
    g_feat[(size_t)g * CDIM + tid] = xv + pos;
}

// ---------------- MLP: f32x2 token pairs, LDS.128 token reads, scalar weight tile ----------------
// dyn smem floats: bufA[256][TPAD] @0 | bufB[256][TPAD] @256*TPAD | Wt[32][257] @2*256*TPAD
#define MLP_SMEM ((2 * 256 * TPAD + 32 * 257) * 4)

template<int TP>
__device__ __forceinline__ void run_layer_t(const float* __restrict__ Wg, float bj,
                                            const float* __restrict__ bufIn,
                                            float* __restrict__ Wt,
                                            unsigned long long acc[TP / 2]) {
    int tid = threadIdx.x;
    unsigned long long binit = pk2(bj, bj);
    #pragma unroll
    for (int p = 0; p < TP / 2; p++) acc[p] = binit;
    for (int kc = 0; kc < 256; kc += 32) {
        // stage transposed weight chunk Wt[k][j] = W[j][kc+k]
        #pragma unroll
        for (int r = 0; r < 8; r++) {
            int e = (r * 256 + tid) * 4;
            int j2 = e >> 5, i = e & 31;
            float4 w4 = *reinterpret_cast<const float4*>(Wg + j2 * 256 + kc + i);
            Wt[(i + 0) * 257 + j2] = w4.x;
            Wt[(i + 1) * 257 + j2] = w4.y;
            Wt[(i + 2) * 257 + j2] = w4.z;
            Wt[(i + 3) * 257 + j2] = w4.w;
        }
        __syncthreads();
        #pragma unroll 8
        for (int k = 0; k < 32; k++) {
            float w = Wt[k * 257 + tid];
            unsigned long long wd = pk2(w, w);
            const ulonglong2* tv = reinterpret_cast<const ulonglong2*>(bufIn + (kc + k) * TPAD);
            #pragma unroll
            for (int p = 0; p < TP / 4; p++) {
                ulonglong2 q = tv[p];
                acc[2 * p]     = fma2(q.x, wd, acc[2 * p]);
                acc[2 * p + 1] = fma2(q.y, wd, acc[2 * p + 1]);
            }
        }
        __syncthreads();
    }
}

template<int TP, int KQ>
__global__ void __launch_bounds__(256) mlp_kernel_t(
    const float* __restrict__ W1, const float* __restrict__ B1,
    const float* __restrict__ W2, const float* __restrict__ B2,
    const float* __restrict__ W3, const float* __restrict__ B3,
    const float* __restrict__ qv, float* __restrict__ outp) {
    extern __shared__ float sh[];
    float* bufA = sh;
    float* bufB = sh + 256 * TPAD;
    float* Wt   = sh + 2 * 256 * TPAD;
    int tid = threadIdx.x;
    int blk = blockIdx.x;

    // coalesced gather from g_feat (k-major: bufA[c][t])
    #pragma unroll
    for (int t = 0; t < TP; t++) {
        int g = blk * TP + t;
        int row = (KQ == KDET) ? g : ((g / KREC) * KDET + (g % KREC));
        bufA[tid * TPAD + t] = g_feat[(size_t)row * CDIM + tid];
    }
    __syncthreads();

    unsigned long long acc[TP / 2];
    run_layer_t<TP>(W1, B1[tid], bufA, Wt, acc);
    #pragma unroll
    for (int p = 0; p < TP / 2; p++) {
        float u, v; upk2(acc[p], u, v);
        *reinterpret_cast<unsigned long long*>(&bufB[tid * TPAD + 2 * p]) =
            pk2(fmaxf(u, 0.f), fmaxf(v, 0.f));
    }
    __syncthreads();

    run_layer_t<TP>(W2, B2[tid], bufB, Wt, acc);
    #pragma unroll
    for (int p = 0; p < TP / 2; p++) {
        float u, v; upk2(acc[p], u, v);
        *reinterpret_cast<unsigned long long*>(&bufA[tid * TPAD + 2 * p]) =
            pk2(fmaxf(u, 0.f), fmaxf(v, 0.f));
    }
    __syncthreads();

    run_layer_t<TP>(W3, B3[tid], bufA, Wt, acc);
    #pragma unroll
    for (int p = 0; p < TP / 2; p++) {
        float u, v; upk2(acc[p], u, v);
        int g0 = blk * TP + 2 * p;
        int qi0 = g0 % KQ, qi1 = (g0 + 1) % KQ;
        outp[(size_t)g0 * 256 + tid]       = u + qv[qi0 * 256 + tid];
        outp[(size_t)(g0 + 1) * 256 + tid] = v + qv[qi1 * 256 + tid];
    }
}

// ---------------- launch ----------------
extern "C" void kernel_launch(void* const* d_in, const int* in_sizes, int n_in,
                              void* d_out, int out_size) {
    const float* x     = (const float*)d_in[0];
    const float* Wc    = (const float*)d_in[1];
    const float* bc    = (const float*)d_in[2];
    const float* Wb    = (const float*)d_in[3];
    const float* bb    = (const float*)d_in[4];
    const float* dW1   = (const float*)d_in[5];
    const float* db1   = (const float*)d_in[6];
    const float* dW2   = (const float*)d_in[7];
    const float* db2   = (const float*)d_in[8];
    const float* dW3   = (const float*)d_in[9];
    const float* db3   = (const float*)d_in[10];
    const float* rW1   = (const float*)d_in[11];
    const float* rb1   = (const float*)d_in[12];
    const float* rW2   = (const float*)d_in[13];
    const float* rb2   = (const float*)d_in[14];
    const float* rW3   = (const float*)d_in[15];
    const float* rb3   = (const float*)d_in[16];
    const float* det_q = (const float*)d_in[17];
    const float* rec_q = (const float*)d_in[18];
    const float* pe    = (const float*)d_in[19];

    float* out = (float*)d_out;
    float* out_det = out;               // 16*100*256 = 409600
    float* out_rec = out + 409600;      // 16*25*256  = 102400
    float* out_cls = out + 512000;      // 16*10000*2 = 320000
    float* out_bb  = out + 832000;      // 16*10000*4 = 640000

    pos_proj_part_kernel<<<(PPARTS * 2500 + 255) / 256, 256>>>(pe, Wc, Wb);
    pos_proj_reduce_kernel<<<(6 * 2500 + 255) / 256, 256>>>();

    main_pass_kernel<<<625, 128>>>(x, bc, bb, Wc, Wb, out_cls, out_bb);

    cudaFuncSetAttribute(topk_kernel, cudaFuncAttributeMaxDynamicSharedMemorySize, TK_SMEM);
    topk_kernel<<<BATCH, 1024, TK_SMEM>>>();

    gather_kernel<<<BATCH * KDET, 256>>>(x, pe);

    cudaFuncSetAttribute(mlp_kernel_t<8, KDET>, cudaFuncAttributeMaxDynamicSharedMemorySize, MLP_SMEM);
    cudaFuncSetAttribute(mlp_kernel_t<8, KREC>, cudaFuncAttributeMaxDynamicSharedMemorySize, MLP_SMEM);
    // det: 1600 tokens / 8 = 200 blocks; rec: 400 tokens / 8 = 50 blocks
    mlp_kernel_t<8, KDET><<<200, 256, MLP_SMEM>>>(dW1, db1, dW2, db2, dW3, db3, det_q, out_det);
    mlp_kernel_t<8, KREC><<<50, 256, MLP_SMEM>>>(rW1, rb1, rW2, rb2, rW3, rb3, rec_q, out_rec);
}

// round 9
// speedup vs baseline: 1.6167x; 1.2466x over previous
#include <cuda_runtime.h>
#include <cstdint>

#define BATCH 16
#define CDIM 256
#define NPIX 10000
#define KDET 100
#define KREC 25
#define TPAD 12

// ---------------- scratch (static device globals) ----------------
__device__ float g_pq[6 * 2500];              // pos projections on 50x50 grid
__device__ float g_peT[2500 * CDIM];          // transposed pos_embed [pix][c]
__device__ unsigned g_keys[BATCH * NPIX];     // monotone-transformed margin keys
__device__ int g_idx[BATCH * KDET];           // top-100 indices per batch
__device__ float g_feat[BATCH * KDET * CDIM]; // gathered x+pos for selected tokens

// ---------------- f32x2 packed helpers ----------------
__device__ __forceinline__ unsigned long long pk2(float a, float b) {
    unsigned long long r;
    asm("mov.b64 %0, {%1,%2};" : "=l"(r) : "f"(a), "f"(b));
    return r;
}
__device__ __forceinline__ void upk2(unsigned long long v, float& a, float& b) {
    asm("mov.b64 {%0,%1}, %2;" : "=f"(a), "=f"(b) : "l"(v));
}
__device__ __forceinline__ unsigned long long fma2(unsigned long long a, unsigned long long b, unsigned long long c) {
    unsigned long long d;
    asm("fma.rn.f32x2 %0, %1, %2, %3;" : "=l"(d) : "l"(a), "l"(b), "l"(c));
    return d;
}
__device__ __forceinline__ unsigned key_xform(float f) {
    unsigned u = __float_as_uint(f);
    return (u & 0x80000000u) ? ~u : (u | 0x80000000u);
}
__device__ __forceinline__ void bil_coord(int o, int& i0, int& i1, float& t) {
    float s = (o + 0.5f) * 0.5f - 0.5f; s = fminf(fmaxf(s, 0.f), 49.f);
    i0 = (int)floorf(s); i1 = min(i0 + 1, 49); t = s - (float)i0;
}

// ---------------- T: transpose pe [256][2500] -> g_peT [2500][256] ----------------
__global__ void peT_kernel(const float* __restrict__ pe) {
    __shared__ float t[32][33];
    int pix0 = blockIdx.x * 32, c0 = blockIdx.y * 32;
    int tx = threadIdx.x, ty = threadIdx.y;   // 32 x 8
    #pragma unroll
    for (int r = 0; r < 4; r++) {
        int c = c0 + ty + r * 8, pix = pix0 + tx;
        if (pix < 2500) t[ty + r * 8][tx] = pe[(size_t)c * 2500 + pix];
    }
    __syncthreads();
    #pragma unroll
    for (int r = 0; r < 4; r++) {
        int pix = pix0 + ty + r * 8, c = c0 + tx;
        if (pix < 2500) g_peT[(size_t)pix * CDIM + c] = t[tx][ty + r * 8];
    }
}

// ---------------- P: project pe (256ch, 50x50) onto 6 weight rows (merged) ----------------
__global__ void pos_proj_kernel(const float* __restrict__ pe,
                                const float* __restrict__ Wc, const float* __restrict__ Wb) {
    __shared__ float ws[6 * 256];
    int tid = threadIdx.x;
    for (int i = tid; i < 512; i += blockDim.x) ws[i] = Wc[i];
    for (int i = tid; i < 1024; i += blockDim.x) ws[512 + i] = Wb[i];
    __syncthreads();
    int pix = blockIdx.x * blockDim.x + tid;
    if (pix >= 2500) return;
    float a0 = 0, a1 = 0, a2 = 0, a3 = 0, a4 = 0, a5 = 0;
    #pragma unroll 8
    for (int c = 0; c < 256; c++) {
        float p = __ldg(pe + (size_t)c * 2500 + pix);
        a0 += p * ws[c];        a1 += p * ws[256 + c];
        a2 += p * ws[512 + c];  a3 += p * ws[768 + c];
        a4 += p * ws[1024 + c]; a5 += p * ws[1280 + c];
    }
    g_pq[pix] = a0;            g_pq[2500 + pix] = a1;
    g_pq[5000 + pix] = a2;     g_pq[7500 + pix] = a3;
    g_pq[10000 + pix] = a4;    g_pq[12500 + pix] = a5;
}

// ---------------- B: stream x once, 2px/thread f32x2, depth-16 double buffer ----------------
__global__ void __launch_bounds__(128) main_pass_kernel(
        const float* __restrict__ x,
        const float* __restrict__ bc, const float* __restrict__ bb,
        const float* __restrict__ Wc, const float* __restrict__ Wb,
        float* __restrict__ out_cls, float* __restrict__ out_bb) {
    __shared__ unsigned long long ws2[6 * 256];
    int tid = threadIdx.x;
    for (int i = tid; i < 1536; i += 128) {
        float v = (i < 512) ? Wc[i] : Wb[i - 512];
        ws2[i] = pk2(v, v);
    }
    __syncthreads();
    int id = blockIdx.x * 128 + tid;
    int b = id / (NPIX / 2);
    int n2 = (id % (NPIX / 2)) * 2;
    const float* base = x + (size_t)b * CDIM * NPIX + n2;
    unsigned long long acc0 = 0, acc1 = 0, acc2 = 0, acc3 = 0, acc4 = 0, acc5 = 0;
    unsigned long long A[16], B[16];
    #pragma unroll
    for (int i = 0; i < 16; i++)
        A[i] = __ldg(reinterpret_cast<const unsigned long long*>(base + (size_t)i * NPIX));
    for (int c0 = 0; c0 < 256; c0 += 32) {
        #pragma unroll
        for (int i = 0; i < 16; i++)
            B[i] = __ldg(reinterpret_cast<const unsigned long long*>(base + (size_t)(c0 + 16 + i) * NPIX));
        #pragma unroll
        for (int i = 0; i < 16; i++) {
            int c = c0 + i;
            unsigned long long v = A[i];
            acc0 = fma2(v, ws2[c], acc0);
            acc1 = fma2(v, ws2[256 + c], acc1);
            acc2 = fma2(v, ws2[512 + c], acc2);
            acc3 = fma2(v, ws2[768 + c], acc3);
            acc4 = fma2(v, ws2[1024 + c], acc4);
            acc5 = fma2(v, ws2[1280 + c], acc5);
        }
        if (c0 + 32 < 256) {
            #pragma unroll
            for (int i = 0; i < 16; i++)
                A[i] = __ldg(reinterpret_cast<const unsigned long long*>(base + (size_t)(c0 + 32 + i) * NPIX));
        }
        #pragma unroll
        for (int i = 0; i < 16; i++) {
            int c = c0 + 16 + i;
            unsigned long long v = B[i];
            acc0 = fma2(v, ws2[c], acc0);
            acc1 = fma2(v, ws2[256 + c], acc1);
            acc2 = fma2(v, ws2[512 + c], acc2);
            acc3 = fma2(v, ws2[768 + c], acc3);
            acc4 = fma2(v, ws2[1024 + c], acc4);
            acc5 = fma2(v, ws2[1280 + c], acc5);
        }
    }
    float a0x, a0y, a1x, a1y, a2x, a2y, a3x, a3y, a4x, a4y, a5x, a5y;
    upk2(acc0, a0x, a0y); upk2(acc1, a1x, a1y); upk2(acc2, a2x, a2y);
    upk2(acc3, a3x, a3y); upk2(acc4, a4x, a4y); upk2(acc5, a5x, a5y);

    // inline bilinear of the 6 projected pos channels at pixels n2, n2+1 (same row)
    int yy = n2 / 100, xxa = n2 % 100;
    int y0, y1, x0a, x1a, x0b, x1b; float ty, txa, txb;
    bil_coord(yy, y0, y1, ty);
    bil_coord(xxa, x0a, x1a, txa);
    bil_coord(xxa + 1, x0b, x1b, txb);
    float pA[6], pB[6];
    #pragma unroll
    for (int w = 0; w < 6; w++) {
        const float* p = g_pq + (size_t)w * 2500;
        float r0a = p[y0 * 50 + x0a] * (1.f - txa) + p[y0 * 50 + x1a] * txa;
        float r1a = p[y1 * 50 + x0a] * (1.f - txa) + p[y1 * 50 + x1a] * txa;
        pA[w] = r0a * (1.f - ty) + r1a * ty;
        float r0b = p[y0 * 50 + x0b] * (1.f - txb) + p[y0 * 50 + x1b] * txb;
        float r1b = p[y1 * 50 + x0b] * (1.f - txb) + p[y1 * 50 + x1b] * txb;
        pB[w] = r0b * (1.f - ty) + r1b * ty;
    }
    float bc0 = bc[0], bc1 = bc[1];
    float bb0 = bb[0], bb1 = bb[1], bb2 = bb[2], bb3 = bb[3];
    float l0x = a0x + pA[0] + bc0, l0y = a0y + pB[0] + bc0;
    float l1x = a1x + pA[1] + bc1, l1y = a1y + pB[1] + bc1;
    size_t co = ((size_t)b * NPIX + n2) * 2;
    *reinterpret_cast<float4*>(out_cls + co) = make_float4(l0x, l1x, l0y, l1y);
    size_t bo = ((size_t)b * NPIX + n2) * 4;
    *reinterpret_cast<float4*>(out_bb + bo) =
        make_float4(a2x + pA[2] + bb0, a3x + pA[3] + bb1, a4x + pA[4] + bb2, a5x + pA[5] + bb3);
    *reinterpret_cast<float4*>(out_bb + bo + 4) =
        make_float4(a2y + pB[2] + bb0, a3y + pB[3] + bb1, a4y + pB[4] + bb2, a5y + pB[5] + bb3);
    uint2 kk = make_uint2(key_xform(l1x - l0x), key_xform(l1y - l0y));
    *reinterpret_cast<uint2*>(g_keys + (size_t)b * NPIX + n2) = kk;
}

// ---------------- C: exact per-batch top-100 (value desc, index asc), 512 threads ----------------
// dyn smem: cand[256] ull @0 | keys[NPIX] u32 @2048 | hist[2048] u32 @42048 | tot[257] u32 @50240
#define TK_SMEM (50240 + 260 * 4)
#define TKT 512
__global__ void __launch_bounds__(TKT) topk_kernel() {
    extern __shared__ char sm[];
    unsigned long long* cand = reinterpret_cast<unsigned long long*>(sm);
    unsigned* keys = reinterpret_cast<unsigned*>(sm + 2048);
    unsigned* histv = reinterpret_cast<unsigned*>(sm + 42048);
    unsigned* tot = reinterpret_cast<unsigned*>(sm + 50240);
    __shared__ unsigned s_prefix;
    __shared__ int s_kk, s_cnt;
    int b = blockIdx.x, tid = threadIdx.x;

    for (int i = tid; i < NPIX; i += TKT) keys[i] = g_keys[(size_t)b * NPIX + i];
    if (tid == 0) { s_prefix = 0u; s_kk = KDET; s_cnt = 0; }
    __syncthreads();

    #pragma unroll
    for (int pass = 0; pass < 4; pass++) {
        int shift = 24 - 8 * pass;
        unsigned himask = (pass == 0) ? 0u : (0xFFFFFFFFu << (shift + 8));
        for (int i = tid; i < 2048; i += TKT) histv[i] = 0;
        __syncthreads();
        unsigned prefix = s_prefix;
        int kk = s_kk;
        unsigned* myh = histv + ((tid >> 5) & 7) * 256;
        for (int i = tid; i < NPIX; i += TKT) {
            unsigned u = keys[i];
            if (((u ^ prefix) & himask) == 0) atomicAdd(&myh[(u >> shift) & 255], 1u);
        }
        __syncthreads();
        if (tid < 256) {
            unsigned s = 0;
            #pragma unroll
            for (int cp = 0; cp < 8; cp++) s += histv[cp * 256 + tid];
            tot[tid] = s;
        }
        __syncthreads();
        // warp 0: suffix scan of 256 bins via shfl (lane l owns bins l*8..l*8+7)
        if (tid < 32) {
            unsigned v[8], gs = 0;
            #pragma unroll
            for (int i = 0; i < 8; i++) { v[i] = tot[tid * 8 + i]; gs += v[i]; }
            unsigned s = gs;
            #pragma unroll
            for (int off = 1; off < 32; off <<= 1) {
                unsigned t = __shfl_down_sync(0xFFFFFFFFu, s, off);
                if (tid + off < 32) s += t;
            }
            unsigned run = s - gs;
            unsigned cum = 0;
            #pragma unroll
            for (int i = 7; i >= 0; i--) {
                cum += v[i];
                tot[tid * 8 + i] = cum + run;
            }
        }
        __syncthreads();
        if (tid < 256) {
            unsigned Sb = tot[tid];
            unsigned Sb1 = (tid < 255) ? tot[tid + 1] : 0u;
            if (Sb >= (unsigned)kk && Sb1 < (unsigned)kk) {
                s_prefix = prefix | ((unsigned)tid << shift);
                s_kk = kk - (int)Sb1;
            }
        }
        __syncthreads();
    }
    unsigned T = s_prefix;

    for (int i = tid; i < NPIX; i += TKT) {
        unsigned u = keys[i];
        if (u >= T) {
            int p = atomicAdd(&s_cnt, 1);
            if (p < 256)
                cand[p] = ((unsigned long long)u << 32) | (unsigned)(~(unsigned)i);
        }
    }
    __syncthreads();
    int cnt = min(s_cnt, 256);
    for (int i = cnt + tid; i < 256; i += TKT) cand[i] = 0ull;
    __syncthreads();

    for (int ksz = 2; ksz <= 256; ksz <<= 1) {
        for (int j = ksz >> 1; j > 0; j >>= 1) {
            if (tid < 256) {
                int l = tid ^ j;
                if (l > tid) {
                    unsigned long long a = cand[tid], c2 = cand[l];
                    bool dirDesc = ((tid & ksz) == 0);
                    if ((a < c2) == dirDesc) { cand[tid] = c2; cand[l] = a; }
                }
            }
            __syncthreads();
        }
    }
    if (tid < KDET)
        g_idx[b * KDET + tid] = (int)(~((unsigned)(cand[tid] & 0xFFFFFFFFull)));
}

// ---------------- G: gather x+pos for 1600 tokens (coalesced pe via g_peT) ----------------
__global__ void __launch_bounds__(256) gather_kernel(const float* __restrict__ x) {
    int g = blockIdx.x;           // 0..1599 : b = g/100
    int tid = threadIdx.x;        // channel
    int idx = g_idx[g];
    int yy = idx / 100, xx = idx % 100;
    int y0, y1, x0, x1; float ty, tx;
    bil_coord(yy, y0, y1, ty);
    bil_coord(xx, x0, x1, tx);
    float v00 = g_peT[(size_t)(y0 * 50 + x0) * CDIM + tid];
    float v01 = g_peT[(size_t)(y0 * 50 + x1) * CDIM + tid];
    float v10 = g_peT[(size_t)(y1 * 50 + x0) * CDIM + tid];
    float v11 = g_peT[(size_t)(y1 * 50 + x1) * CDIM + tid];
    float r0 = v00 * (1.f - ty) + v10 * ty;
    float r1 = v01 * (1.f - ty) + v11 * ty;
    float pos = r0 * (1.f - tx) + r1 * tx;
    int b = g / KDET;
    float xv = __ldg(x + ((size_t)(b * CDIM + tid)) * NPIX + idx);
    g_feat[(size_t)g * CDIM + tid] = xv + pos;
}

// ---------------- MLP: det+rec fused in one launch; f32x2; TP=8 ----------------
#define MLP_SMEM ((2 * 256 * TPAD + 32 * 257) * 4)
#define TP 8
#define DET_BLOCKS 200

__device__ __forceinline__ void run_layer8(const float* __restrict__ Wg, float bj,
                                           const float* __restrict__ bufIn,
                                           float* __restrict__ Wt,
                                           unsigned long long acc[4]) {
    int tid = threadIdx.x;
    unsigned long long binit = pk2(bj, bj);
    #pragma unroll
    for (int p = 0; p < 4; p++) acc[p] = binit;
    for (int kc = 0; kc < 256; kc += 32) {
        #pragma unroll
        for (int r = 0; r < 8; r++) {
            int e = (r * 256 + tid) * 4;
            int j2 = e >> 5, i = e & 31;
            float4 w4 = *reinterpret_cast<const float4*>(Wg + j2 * 256 + kc + i);
            Wt[(i + 0) * 257 + j2] = w4.x;
            Wt[(i + 1) * 257 + j2] = w4.y;
            Wt[(i + 2) * 257 + j2] = w4.z;
            Wt[(i + 3) * 257 + j2] = w4.w;
        }
        __syncthreads();
        #pragma unroll 8
        for (int k = 0; k < 32; k++) {
            float w = Wt[k * 257 + tid];
            unsigned long long wd = pk2(w, w);
            const ulonglong2* tv = reinterpret_cast<const ulonglong2*>(bufIn + (kc + k) * TPAD);
            ulonglong2 q0 = tv[0], q1 = tv[1];
            acc[0] = fma2(q0.x, wd, acc[0]);
            acc[1] = fma2(q0.y, wd, acc[1]);
            acc[2] = fma2(q1.x, wd, acc[2]);
            acc[3] = fma2(q1.y, wd, acc[3]);
        }
        __syncthreads();
    }
}

__global__ void __launch_bounds__(256) mlp_kernel(
    const float* __restrict__ dW1, const float* __restrict__ db1,
    const float* __restrict__ dW2, const float* __restrict__ db2,
    const float* __restrict__ dW3, const float* __restrict__ db3,
    const float* __restrict__ rW1, const float* __restrict__ rb1,
    const float* __restrict__ rW2, const float* __restrict__ rb2,
    const float* __restrict__ rW3, const float* __restrict__ rb3,
    const float* __restrict__ det_q, const float* __restrict__ rec_q,
    float* __restrict__ out_det, float* __restrict__ out_rec) {
    extern __shared__ float sh[];
    float* bufA = sh;
    float* bufB = sh + 256 * TPAD;
    float* Wt   = sh + 2 * 256 * TPAD;
    int tid = threadIdx.x;
    bool isDet = blockIdx.x < DET_BLOCKS;
    int blk = isDet ? blockIdx.x : (blockIdx.x - DET_BLOCKS);
    int kq = isDet ? KDET : KREC;

    #pragma unroll
    for (int t = 0; t < TP; t++) {
        int g = blk * TP + t;
        int row = isDet ? g : ((g / KREC) * KDET + (g % KREC));
        bufA[tid * TPAD + t] = g_feat[(size_t)row * CDIM + tid];
    }
    __syncthreads();

    const float* W1 = isDet ? dW1 : rW1; const float* B1 = isDet ? db1 : rb1;
    const float* W2 = isDet ? dW2 : rW2; const float* B2 = isDet ? db2 : rb2;
    const float* W3 = isDet ? dW3 : rW3; const float* B3 = isDet ? db3 : rb3;
    const float* qv = isDet ? det_q : rec_q;
    float* outp = isDet ? out_det : out_rec;

    unsigned long long acc[4];
    run_layer8(W1, B1[tid], bufA, Wt, acc);
    #pragma unroll
    for (int p = 0; p < 4; p++) {
        float u, v; upk2(acc[p], u, v);
        *reinterpret_cast<unsigned long long*>(&bufB[tid * TPAD + 2 * p]) =
            pk2(fmaxf(u, 0.f), fmaxf(v, 0.f));
    }
    __syncthreads();

    run_layer8(W2, B2[tid], bufB, Wt, acc);
    #pragma unroll
    for (int p = 0; p < 4; p++) {
        float u, v; upk2(acc[p], u, v);
        *reinterpret_cast<unsigned long long*>(&bufA[tid * TPAD + 2 * p]) =
            pk2(fmaxf(u, 0.f), fmaxf(v, 0.f));
    }
    __syncthreads();

    run_layer8(W3, B3[tid], bufA, Wt, acc);
    #pragma unroll
    for (int p = 0; p < 4; p++) {
        float u, v; upk2(acc[p], u, v);
        int g0 = blk * TP + 2 * p;
        int qi0 = g0 % kq, qi1 = (g0 + 1) % kq;
        outp[(size_t)g0 * 256 + tid]       = u + qv[qi0 * 256 + tid];
        outp[(size_t)(g0 + 1) * 256 + tid] = v + qv[qi1 * 256 + tid];
    }
}

// ---------------- launch ----------------
extern "C" void kernel_launch(void* const* d_in, const int* in_sizes, int n_in,
                              void* d_out, int out_size) {
    const float* x     = (const float*)d_in[0];
    const float* Wc    = (const float*)d_in[1];
    const float* bc    = (const float*)d_in[2];
    const float* Wb    = (const float*)d_in[3];
    const float* bb    = (const float*)d_in[4];
    const float* dW1   = (const float*)d_in[5];
    const float* db1   = (const float*)d_in[6];
    const float* dW2   = (const float*)d_in[7];
    const float* db2   = (const float*)d_in[8];
    const float* dW3   = (const float*)d_in[9];
    const float* db3   = (const float*)d_in[10];
    const float* rW1   = (const float*)d_in[11];
    const float* rb1   = (const float*)d_in[12];
    const float* rW2   = (const float*)d_in[13];
    const float* rb2   = (const float*)d_in[14];
    const float* rW3   = (const float*)d_in[15];
    const float* rb3   = (const float*)d_in[16];
    const float* det_q = (const float*)d_in[17];
    const float* rec_q = (const float*)d_in[18];
    const float* pe    = (const float*)d_in[19];

    float* out = (float*)d_out;
    float* out_det = out;               // 16*100*256 = 409600
    float* out_rec = out + 409600;      // 16*25*256  = 102400
    float* out_cls = out + 512000;      // 16*10000*2 = 320000
    float* out_bb  = out + 832000;      // 16*10000*4 = 640000

    dim3 tgrid(79, 8), tblk(32, 8);
    peT_kernel<<<tgrid, tblk>>>(pe);
    pos_proj_kernel<<<20, 128>>>(pe, Wc, Wb);
    main_pass_kernel<<<625, 128>>>(x, bc, bb, Wc, Wb, out_cls, out_bb);

    cudaFuncSetAttribute(topk_kernel, cudaFuncAttributeMaxDynamicSharedMemorySize, TK_SMEM);
    topk_kernel<<<BATCH, TKT, TK_SMEM>>>();

    gather_kernel<<<BATCH * KDET, 256>>>(x);

    cudaFuncSetAttribute(mlp_kernel, cudaFuncAttributeMaxDynamicSharedMemorySize, MLP_SMEM);
    mlp_kernel<<<250, 256, MLP_SMEM>>>(dW1, db1, dW2, db2, dW3, db3,
                                       rW1, rb1, rW2, rb2, rW3, rb3,
                                       det_q, rec_q, out_det, out_rec);
}

// round 11
// speedup vs baseline: 1.6391x; 1.0139x over previous
#include <cuda_runtime.h>
#include <cstdint>

#define BATCH 16
#define CDIM 256
#define NPIX 10000
#define KDET 100
#define KREC 25
#define TPAD 12

// ---------------- scratch (static device globals) ----------------
__device__ float g_pq[6 * 2500];              // pos projections on 50x50 grid
__device__ float g_peT[2500 * CDIM];          // transposed pos_embed [pix][c]
__device__ unsigned g_keys[BATCH * NPIX];     // monotone-transformed margin keys
__device__ int g_idx[BATCH * KDET];           // top-100 indices per batch

// ---------------- f32x2 packed helpers ----------------
__device__ __forceinline__ unsigned long long pk2(float a, float b) {
    unsigned long long r;
    asm("mov.b64 %0, {%1,%2};" : "=l"(r) : "f"(a), "f"(b));
    return r;
}
__device__ __forceinline__ void upk2(unsigned long long v, float& a, float& b) {
    asm("mov.b64 {%0,%1}, %2;" : "=f"(a), "=f"(b) : "l"(v));
}
__device__ __forceinline__ unsigned long long fma2(unsigned long long a, unsigned long long b, unsigned long long c) {
    unsigned long long d;
    asm("fma.rn.f32x2 %0, %1, %2, %3;" : "=l"(d) : "l"(a), "l"(b), "l"(c));
    return d;
}
__device__ __forceinline__ unsigned key_xform(float f) {
    unsigned u = __float_as_uint(f);
    return (u & 0x80000000u) ? ~u : (u | 0x80000000u);
}
__device__ __forceinline__ void bil_coord(int o, int& i0, int& i1, float& t) {
    float s = (o + 0.5f) * 0.5f - 0.5f; s = fminf(fmaxf(s, 0.f), 49.f);
    i0 = (int)floorf(s); i1 = min(i0 + 1, 49); t = s - (float)i0;
}

// ---------------- T: transpose pe [256][2500] -> g_peT [2500][256] ----------------
__global__ void peT_kernel(const float* __restrict__ pe) {
    __shared__ float t[32][33];
    int pix0 = blockIdx.x * 32, c0 = blockIdx.y * 32;
    int tx = threadIdx.x, ty = threadIdx.y;   // 32 x 8
    #pragma unroll
    for (int r = 0; r < 4; r++) {
        int c = c0 + ty + r * 8, pix = pix0 + tx;
        if (pix < 2500) t[ty + r * 8][tx] = pe[(size_t)c * 2500 + pix];
    }
    __syncthreads();
    #pragma unroll
    for (int r = 0; r < 4; r++) {
        int pix = pix0 + ty + r * 8, c = c0 + tx;
        if (pix < 2500) g_peT[(size_t)pix * CDIM + c] = t[tx][ty + r * 8];
    }
}

// ---------------- P: project pe (256ch, 50x50) onto 6 weight rows ----------------
__global__ void pos_proj_kernel(const float* __restrict__ pe,
                                const float* __restrict__ Wc, const float* __restrict__ Wb) {
    __shared__ float ws[6 * 256];
    int tid = threadIdx.x;
    for (int i = tid; i < 512; i += blockDim.x) ws[i] = Wc[i];
    for (int i = tid; i < 1024; i += blockDim.x) ws[512 + i] = Wb[i];
    __syncthreads();
    int pix = blockIdx.x * blockDim.x + tid;
    if (pix >= 2500) return;
    float a0 = 0, a1 = 0, a2 = 0, a3 = 0, a4 = 0, a5 = 0;
    #pragma unroll 8
    for (int c = 0; c < 256; c++) {
        float p = __ldg(pe + (size_t)c * 2500 + pix);
        a0 += p * ws[c];        a1 += p * ws[256 + c];
        a2 += p * ws[512 + c];  a3 += p * ws[768 + c];
        a4 += p * ws[1024 + c]; a5 += p * ws[1280 + c];
    }
    g_pq[pix] = a0;            g_pq[2500 + pix] = a1;
    g_pq[5000 + pix] = a2;     g_pq[7500 + pix] = a3;
    g_pq[10000 + pix] = a4;    g_pq[12500 + pix] = a5;
}

// ---------------- B: stream x once, 2px/thread f32x2, depth-16 double buffer ----------------
__global__ void __launch_bounds__(128) main_pass_kernel(
        const float* __restrict__ x,
        const float* __restrict__ bc, const float* __restrict__ bb,
        const float* __restrict__ Wc, const float* __restrict__ Wb,
        float* __restrict__ out_cls, float* __restrict__ out_bb) {
    __shared__ unsigned long long ws2[6 * 256];
    int tid = threadIdx.x;
    for (int i = tid; i < 1536; i += 128) {
        float v = (i < 512) ? Wc[i] : Wb[i - 512];
        ws2[i] = pk2(v, v);
    }
    __syncthreads();
    int id = blockIdx.x * 128 + tid;
    int b = id / (NPIX / 2);
    int n2 = (id % (NPIX / 2)) * 2;
    const float* base = x + (size_t)b * CDIM * NPIX + n2;
    unsigned long long acc0 = 0, acc1 = 0, acc2 = 0, acc3 = 0, acc4 = 0, acc5 = 0;
    unsigned long long A[16], B[16];
    #pragma unroll
    for (int i = 0; i < 16; i++)
        A[i] = __ldg(reinterpret_cast<const unsigned long long*>(base + (size_t)i * NPIX));
    for (int c0 = 0; c0 < 256; c0 += 32) {
        #pragma unroll
        for (int i = 0; i < 16; i++)
            B[i] = __ldg(reinterpret_cast<const unsigned long long*>(base + (size_t)(c0 + 16 + i) * NPIX));
        #pragma unroll
        for (int i = 0; i < 16; i++) {
            int c = c0 + i;
            unsigned long long v = A[i];
            acc0 = fma2(v, ws2[c], acc0);
            acc1 = fma2(v, ws2[256 + c], acc1);
            acc2 = fma2(v, ws2[512 + c], acc2);
            acc3 = fma2(v, ws2[768 + c], acc3);
            acc4 = fma2(v, ws2[1024 + c], acc4);
            acc5 = fma2(v, ws2[1280 + c], acc5);
        }
        if (c0 + 32 < 256) {
            #pragma unroll
            for (int i = 0; i < 16; i++)
                A[i] = __ldg(reinterpret_cast<const unsigned long long*>(base + (size_t)(c0 + 32 + i) * NPIX));
        }
        #pragma unroll
        for (int i = 0; i < 16; i++) {
            int c = c0 + 16 + i;
            unsigned long long v = B[i];
            acc0 = fma2(v, ws2[c], acc0);
            acc1 = fma2(v, ws2[256 + c], acc1);
            acc2 = fma2(v, ws2[512 + c], acc2);
            acc3 = fma2(v, ws2[768 + c], acc3);
            acc4 = fma2(v, ws2[1024 + c], acc4);
            acc5 = fma2(v, ws2[1280 + c], acc5);
        }
    }
    float a0x, a0y, a1x, a1y, a2x, a2y, a3x, a3y, a4x, a4y, a5x, a5y;
    upk2(acc0, a0x, a0y); upk2(acc1, a1x, a1y); upk2(acc2, a2x, a2y);
    upk2(acc3, a3x, a3y); upk2(acc4, a4x, a4y); upk2(acc5, a5x, a5y);

    int yy = n2 / 100, xxa = n2 % 100;
    int y0, y1, x0a, x1a, x0b, x1b; float ty, txa, txb;
    bil_coord(yy, y0, y1, ty);
    bil_coord(xxa, x0a, x1a, txa);
    bil_coord(xxa + 1, x0b, x1b, txb);
    float pA[6], pB[6];
    #pragma unroll
    for (int w = 0; w < 6; w++) {
        const float* p = g_pq + (size_t)w * 2500;
        float r0a = p[y0 * 50 + x0a] * (1.f - txa) + p[y0 * 50 + x1a] * txa;
        float r1a = p[y1 * 50 + x0a] * (1.f - txa) + p[y1 * 50 + x1a] * txa;
        pA[w] = r0a * (1.f - ty) + r1a * ty;
        float r0b = p[y0 * 50 + x0b] * (1.f - txb) + p[y0 * 50 + x1b] * txb;
        float r1b = p[y1 * 50 + x0b] * (1.f - txb) + p[y1 * 50 + x1b] * txb;
        pB[w] = r0b * (1.f - ty) + r1b * ty;
    }
    float bc0 = bc[0], bc1 = bc[1];
    float bb0 = bb[0], bb1 = bb[1], bb2 = bb[2], bb3 = bb[3];
    float l0x = a0x + pA[0] + bc0, l0y = a0y + pB[0] + bc0;
    float l1x = a1x + pA[1] + bc1, l1y = a1y + pB[1] + bc1;
    size_t co = ((size_t)b * NPIX + n2) * 2;
    *reinterpret_cast<float4*>(out_cls + co) = make_float4(l0x, l1x, l0y, l1y);
    size_t bo = ((size_t)b * NPIX + n2) * 4;
    *reinterpret_cast<float4*>(out_bb + bo) =
        make_float4(a2x + pA[2] + bb0, a3x + pA[3] + bb1, a4x + pA[4] + bb2, a5x + pA[5] + bb3);
    *reinterpret_cast<float4*>(out_bb + bo + 4) =
        make_float4(a2y + pB[2] + bb0, a3y + pB[3] + bb1, a4y + pB[4] + bb2, a5y + pB[5] + bb3);
    uint2 kk = make_uint2(key_xform(l1x - l0x), key_xform(l1y - l0y));
    *reinterpret_cast<uint2*>(g_keys + (size_t)b * NPIX + n2) = kk;
}

// ---------------- C: exact per-batch top-100 with candidate compaction ----------------
#define TKT 1024
#define COMP_CAP 2048
__global__ void __launch_bounds__(TKT) topk_kernel() {
    __shared__ unsigned long long comp[COMP_CAP];
    __shared__ unsigned long long cand[256];
    __shared__ unsigned hist[2048];
    __shared__ unsigned tot[256];
    __shared__ unsigned s_prefix;
    __shared__ int s_kk, s_cnt, s_m;
    int b = blockIdx.x, tid = threadIdx.x;
    const unsigned* gk = g_keys + (size_t)b * NPIX;
    unsigned* myh = hist + ((tid >> 5) & 7) * 256;

    if (tid == 0) { s_prefix = 0u; s_kk = KDET; s_cnt = 0; s_m = 0; }
    for (int i = tid; i < 2048; i += TKT) hist[i] = 0;
    __syncthreads();

    // ---- pass 0: full scan, histogram top byte ----
    for (int i = tid; i < NPIX; i += TKT) atomicAdd(&myh[gk[i] >> 24], 1u);
    __syncthreads();
    // merge + warp suffix scan + select
    if (tid < 256) {
        unsigned s = 0;
        #pragma unroll
        for (int cp = 0; cp < 8; cp++) s += hist[cp * 256 + tid];
        tot[tid] = s;
    }
    __syncthreads();
    if (tid < 32) {
        unsigned v[8], gs = 0;
        #pragma unroll
        for (int i = 0; i < 8; i++) { v[i] = tot[tid * 8 + i]; gs += v[i]; }
        unsigned s = gs;
        #pragma unroll
        for (int off = 1; off < 32; off <<= 1) {
            unsigned t = __shfl_down_sync(0xFFFFFFFFu, s, off);
            if (tid + off < 32) s += t;
        }
        unsigned run = s - gs, cum = 0;
        #pragma unroll
        for (int i = 7; i >= 0; i--) { cum += v[i]; tot[tid * 8 + i] = cum + run; }
    }
    __syncthreads();
    if (tid < 256) {
        unsigned Sb = tot[tid];
        unsigned Sb1 = (tid < 255) ? tot[tid + 1] : 0u;
        if (Sb >= (unsigned)KDET && Sb1 < (unsigned)KDET) {
            s_prefix = (unsigned)tid << 24;
            s_kk = KDET - (int)Sb1;
        }
    }
    __syncthreads();
    unsigned sel1 = s_prefix >> 24;

    // ---- compact all keys with top byte >= sel1 ----
    for (int i = tid; i < NPIX; i += TKT) {
        unsigned u = gk[i];
        if ((u >> 24) >= sel1) {
            int p = atomicAdd(&s_m, 1);
            if (p < COMP_CAP)
                comp[p] = ((unsigned long long)u << 32) | (unsigned)(~(unsigned)i);
        }
    }
    __syncthreads();
    bool ok = (s_m <= COMP_CAP);
    int M = ok ? s_m : NPIX;

    // ---- passes 1-3 over compacted list (or fallback full scan) ----
    for (int pass = 1; pass < 4; pass++) {
        int shift = 24 - 8 * pass;
        unsigned himask = 0xFFFFFFFFu << (shift + 8);
        for (int i = tid; i < 2048; i += TKT) hist[i] = 0;
        __syncthreads();
        unsigned prefix = s_prefix;
        int kk = s_kk;
        for (int i = tid; i < M; i += TKT) {
            unsigned u = ok ? (unsigned)(comp[i] >> 32) : gk[i];
            if (((u ^ prefix) & himask) == 0) atomicAdd(&myh[(u >> shift) & 255], 1u);
        }
        __syncthreads();
        if (tid < 256) {
            unsigned s = 0;
            #pragma unroll
            for (int cp = 0; cp < 8; cp++) s += hist[cp * 256 + tid];
            tot[tid] = s;
        }
        __syncthreads();
        if (tid < 32) {
            unsigned v[8], gs = 0;
            #pragma unroll
            for (int i = 0; i < 8; i++) { v[i] = tot[tid * 8 + i]; gs += v[i]; }
            unsigned s = gs;
            #pragma unroll
            for (int off = 1; off < 32; off <<= 1) {
                unsigned t = __shfl_down_sync(0xFFFFFFFFu, s, off);
                if (tid + off < 32) s += t;
            }
            unsigned run = s - gs, cum = 0;
            #pragma unroll
            for (int i = 7; i >= 0; i--) { cum += v[i]; tot[tid * 8 + i] = cum + run; }
        }
        __syncthreads();
        if (tid < 256) {
            unsigned Sb = tot[tid];
            unsigned Sb1 = (tid < 255) ? tot[tid + 1] : 0u;
            if (Sb >= (unsigned)kk && Sb1 < (unsigned)kk) {
                s_prefix = prefix | ((unsigned)tid << shift);
                s_kk = kk - (int)Sb1;
            }
        }
        __syncthreads();
    }
    unsigned T = s_prefix;

    // ---- collect candidates >= T ----
    for (int i = tid; i < M; i += TKT) {
        unsigned long long e; unsigned u;
        if (ok) { e = comp[i]; u = (unsigned)(e >> 32); }
        else { u = gk[i]; e = ((unsigned long long)u << 32) | (unsigned)(~(unsigned)i); }
        if (u >= T) {
            int p = atomicAdd(&s_cnt, 1);
            if (p < 256) cand[p] = e;
        }
    }
    __syncthreads();
    int cnt = min(s_cnt, 256);
    for (int i = cnt + tid; i < 256; i += TKT) cand[i] = 0ull;
    __syncthreads();

    // bitonic sort 256 descending => value desc, index asc on ties
    for (int ksz = 2; ksz <= 256; ksz <<= 1) {
        for (int j = ksz >> 1; j > 0; j >>= 1) {
            if (tid < 256) {
                int l = tid ^ j;
                if (l > tid) {
                    unsigned long long a = cand[tid], c2 = cand[l];
                    bool dirDesc = ((tid & ksz) == 0);
                    if ((a < c2) == dirDesc) { cand[tid] = c2; cand[l] = a; }
                }
            }
            __syncthreads();
        }
    }
    if (tid < KDET)
        g_idx[b * KDET + tid] = (int)(~((unsigned)(cand[tid] & 0xFFFFFFFFull)));
}

// ---------------- MLP: fused gather + det/rec in one launch; f32x2; TP=8 ----------------
#define MLP_SMEM ((2 * 256 * TPAD + 32 * 257) * 4)
#define TP 8
#define DET_BLOCKS 200

__device__ __forceinline__ void run_layer8(const float* __restrict__ Wg, float bj,
                                           const float* __restrict__ bufIn,
                                           float* __restrict__ Wt,
                                           unsigned long long acc[4]) {
    int tid = threadIdx.x;
    unsigned long long binit = pk2(bj, bj);
    #pragma unroll
    for (int p = 0; p < 4; p++) acc[p] = binit;
    for (int kc = 0; kc < 256; kc += 32) {
        #pragma unroll
        for (int r = 0; r < 8; r++) {
            int e = (r * 256 + tid) * 4;
            int j2 = e >> 5, i = e & 31;
            float4 w4 = *reinterpret_cast<const float4*>(Wg + j2 * 256 + kc + i);
            Wt[(i + 0) * 257 + j2] = w4.x;
            Wt[(i + 1) * 257 + j2] = w4.y;
            Wt[(i + 2) * 257 + j2] = w4.z;
            Wt[(i + 3) * 257 + j2] = w4.w;
        }
        __syncthreads();
        #pragma unroll 8
        for (int k = 0; k < 32; k++) {
            float w = Wt[k * 257 + tid];
            unsigned long long wd = pk2(w, w);
            const ulonglong2* tv = reinterpret_cast<const ulonglong2*>(bufIn + (kc + k) * TPAD);
            ulonglong2 q0 = tv[0], q1 = tv[1];
            acc[0] = fma2(q0.x, wd, acc[0]);
            acc[1] = fma2(q0.y, wd, acc[1]);
            acc[2] = fma2(q1.x, wd, acc[2]);
            acc[3] = fma2(q1.y, wd, acc[3]);
        }
        __syncthreads();
    }
}

__global__ void __launch_bounds__(256) mlp_kernel(
    const float* __restrict__ x,
    const float* __restrict__ dW1, const float* __restrict__ db1,
    const float* __restrict__ dW2, const float* __restrict__ db2,
    const float* __restrict__ dW3, const float* __restrict__ db3,
    const float* __restrict__ rW1, const float* __restrict__ rb1,
    const float* __restrict__ rW2, const float* __restrict__ rb2,
    const float* __restrict__ rW3, const float* __restrict__ rb3,
    const float* __restrict__ det_q, const float* __restrict__ rec_q,
    float* __restrict__ out_det, float* __restrict__ out_rec) {
    extern __shared__ float sh[];
    float* bufA = sh;
    float* bufB = sh + 256 * TPAD;
    float* Wt   = sh + 2 * 256 * TPAD;
    int tid = threadIdx.x;
    bool isDet = blockIdx.x < DET_BLOCKS;
    int blk = isDet ? blockIdx.x : (blockIdx.x - DET_BLOCKS);
    int kq = isDet ? KDET : KREC;

    // fused gather: x[b,:,idx] + bilinear(peT) for this block's 8 tokens
    #pragma unroll
    for (int t = 0; t < TP; t++) {
        int g = blk * TP + t;
        int bq = isDet ? g : ((g / KREC) * KDET + (g % KREC));
        int idx = g_idx[bq];
        int bb_ = bq / KDET;
        int yy = idx / 100, xx = idx % 100;
        int y0, y1, x0, x1; float ty, tx;
        bil_coord(yy, y0, y1, ty);
        bil_coord(xx, x0, x1, tx);
        float v00 = g_peT[(size_t)(y0 * 50 + x0) * CDIM + tid];
        float v01 = g_peT[(size_t)(y0 * 50 + x1) * CDIM + tid];
        float v10 = g_peT[(size_t)(y1 * 50 + x0) * CDIM + tid];
        float v11 = g_peT[(size_t)(y1 * 50 + x1) * CDIM + tid];
        float r0 = v00 * (1.f - ty) + v10 * ty;
        float r1 = v01 * (1.f - ty) + v11 * ty;
        float pos = r0 * (1.f - tx) + r1 * tx;
        float xv = __ldg(x + ((size_t)(bb_ * CDIM + tid)) * NPIX + idx);
        bufA[tid * TPAD + t] = xv + pos;
    }
    __syncthreads();

    const float* W1 = isDet ? dW1 : rW1; const float* B1 = isDet ? db1 : rb1;
    const float* W2 = isDet ? dW2 : rW2; const float* B2 = isDet ? db2 : rb2;
    const float* W3 = isDet ? dW3 : rW3; const float* B3 = isDet ? db3 : rb3;
    const float* qv = isDet ? det_q : rec_q;
    float* outp = isDet ? out_det : out_rec;

    unsigned long long acc[4];
    run_layer8(W1, B1[tid], bufA, Wt, acc);
    #pragma unroll
    for (int p = 0; p < 4; p++) {
        float u, v; upk2(acc[p], u, v);
        *reinterpret_cast<unsigned long long*>(&bufB[tid * TPAD + 2 * p]) =
            pk2(fmaxf(u, 0.f), fmaxf(v, 0.f));
    }
    __syncthreads();

    run_layer8(W2, B2[tid], bufB, Wt, acc);
    #pragma unroll
    for (int p = 0; p < 4; p++) {
        float u, v; upk2(acc[p], u, v);
        *reinterpret_cast<unsigned long long*>(&bufA[tid * TPAD + 2 * p]) =
            pk2(fmaxf(u, 0.f), fmaxf(v, 0.f));
    }
    __syncthreads();

    run_layer8(W3, B3[tid], bufA, Wt, acc);
    #pragma unroll
    for (int p = 0; p < 4; p++) {
        float u, v; upk2(acc[p], u, v);
        int g0 = blk * TP + 2 * p;
        int qi0 = g0 % kq, qi1 = (g0 + 1) % kq;
        outp[(size_t)g0 * 256 + tid]       = u + qv[qi0 * 256 + tid];
        outp[(size_t)(g0 + 1) * 256 + tid] = v + qv[qi1 * 256 + tid];
    }
}

// ---------------- launch ----------------
extern "C" void kernel_launch(void* const* d_in, const int* in_sizes, int n_in,
                              void* d_out, int out_size) {
    const float* x     = (const float*)d_in[0];
    const float* Wc    = (const float*)d_in[1];
    const float* bc    = (const float*)d_in[2];
    const float* Wb    = (const float*)d_in[3];
    const float* bb    = (const float*)d_in[4];
    const float* dW1   = (const float*)d_in[5];
    const float* db1   = (const float*)d_in[6];
    const float* dW2   = (const float*)d_in[7];
    const float* db2   = (const float*)d_in[8];
    const float* dW3   = (const float*)d_in[9];
    const float* db3   = (const float*)d_in[10];
    const float* rW1   = (const float*)d_in[11];
    const float* rb1   = (const float*)d_in[12];
    const float* rW2   = (const float*)d_in[13];
    const float* rb2   = (const float*)d_in[14];
    const float* rW3   = (const float*)d_in[15];
    const float* rb3   = (const float*)d_in[16];
    const float* det_q = (const float*)d_in[17];
    const float* rec_q = (const float*)d_in[18];
    const float* pe    = (const float*)d_in[19];

    float* out = (float*)d_out;
    float* out_det = out;               // 16*100*256 = 409600
    float* out_rec = out + 409600;      // 16*25*256  = 102400
    float* out_cls = out + 512000;      // 16*10000*2 = 320000
    float* out_bb  = out + 832000;      // 16*10000*4 = 640000

    dim3 tgrid(79, 8), tblk(32, 8);
    peT_kernel<<<tgrid, tblk>>>(pe);
    pos_proj_kernel<<<20, 128>>>(pe, Wc, Wb);
    main_pass_kernel<<<625, 128>>>(x, bc, bb, Wc, Wb, out_cls, out_bb);
    topk_kernel<<<BATCH, TKT>>>();

    cudaFuncSetAttribute(mlp_kernel, cudaFuncAttributeMaxDynamicSharedMemorySize, MLP_SMEM);
    mlp_kernel<<<250, 256, MLP_SMEM>>>(x, dW1, db1, dW2, db2, dW3, db3,
                                       rW1, rb1, rW2, rb2, rW3, rb3,
                                       det_q, rec_q, out_det, out_rec);
}